// round 1
// baseline (speedup 1.0000x reference)
#include <cuda_runtime.h>
#include <cuda_bf16.h>

#define LQ 9216
#define C 768
#define NH 6
#define DH 128
#define NP 4
#define GRID 96

// ---------------- scratch (no allocations allowed) ----------------
__device__ float g_qn[LQ * C];
__device__ float g_fn[LQ * C];
__device__ float g_val[LQ * C];
__device__ float g_samp[LQ * C];
__device__ float g_q1[LQ * C];
__device__ float g_oa[LQ * 72];

// ---------------- LayerNorm: one block per row, 256 threads ----------------
__global__ __launch_bounds__(256) void ln_kernel(const float* __restrict__ x,
                                                 const float* __restrict__ w,
                                                 const float* __restrict__ b,
                                                 float* __restrict__ y) {
    int row = blockIdx.x;
    int t = threadIdx.x;
    const float* xr = x + row * C;
    float v0 = xr[t], v1 = xr[t + 256], v2 = xr[t + 512];

    __shared__ float red[256];
    red[t] = v0 + v1 + v2;
    __syncthreads();
    #pragma unroll
    for (int o = 128; o > 0; o >>= 1) {
        if (t < o) red[t] += red[t + o];
        __syncthreads();
    }
    float mu = red[0] * (1.0f / C);
    __syncthreads();

    float d0 = v0 - mu, d1 = v1 - mu, d2 = v2 - mu;
    red[t] = d0 * d0 + d1 * d1 + d2 * d2;
    __syncthreads();
    #pragma unroll
    for (int o = 128; o > 0; o >>= 1) {
        if (t < o) red[t] += red[t + o];
        __syncthreads();
    }
    float rs = rsqrtf(red[0] * (1.0f / C) + 1e-6f);

    float* yr = y + row * C;
    yr[t]       = d0 * rs * w[t]       + b[t];
    yr[t + 256] = d1 * rs * w[t + 256] + b[t + 256];
    yr[t + 512] = d2 * rs * w[t + 512] + b[t + 512];
}

// ---------------- Tiled fp32 GEMM: C[m,n] = sum_k A[m,k]*B[n,k] + bias[n] ----
// EPI: C[m,n] = resid[m,n] + gamma[n] * (dot + bias[n])
#define BM 128
#define BN 64
#define BK 16

template <bool EPI>
__global__ __launch_bounds__(256) void gemm_tn(const float* __restrict__ A,
                                               const float* __restrict__ B,
                                               const float* __restrict__ bias,
                                               const float* __restrict__ resid,
                                               const float* __restrict__ gamma,
                                               float* __restrict__ Cout,
                                               int M, int N, int K) {
    __shared__ float As[BK][BM];
    __shared__ float Bs[BK][BN];

    int tid = threadIdx.x;
    int bm = blockIdx.y * BM;
    int bn = blockIdx.x * BN;
    int tidm = tid >> 4;   // 0..15 -> 8 rows each
    int tidn = tid & 15;   // 0..15 -> 4 cols each

    float acc[8][4] = {};

    for (int k0 = 0; k0 < K; k0 += BK) {
        // A tile: 128x16 = 512 float4, 2 per thread
        #pragma unroll
        for (int i = 0; i < 2; i++) {
            int slot = tid + i * 256;
            int r = slot >> 2;
            int c4 = (slot & 3) << 2;
            float4 v = *(const float4*)(A + (size_t)(bm + r) * K + k0 + c4);
            As[c4 + 0][r] = v.x;
            As[c4 + 1][r] = v.y;
            As[c4 + 2][r] = v.z;
            As[c4 + 3][r] = v.w;
        }
        // B tile: 64x16 = 256 float4, 1 per thread
        {
            int r = tid >> 2;
            int c4 = (tid & 3) << 2;
            float4 v = *(const float4*)(B + (size_t)(bn + r) * K + k0 + c4);
            Bs[c4 + 0][r] = v.x;
            Bs[c4 + 1][r] = v.y;
            Bs[c4 + 2][r] = v.z;
            Bs[c4 + 3][r] = v.w;
        }
        __syncthreads();

        #pragma unroll
        for (int k = 0; k < BK; k++) {
            float4 a0 = *(const float4*)&As[k][tidm * 8];
            float4 a1 = *(const float4*)&As[k][tidm * 8 + 4];
            float4 b0 = *(const float4*)&Bs[k][tidn * 4];
            float a[8] = {a0.x, a0.y, a0.z, a0.w, a1.x, a1.y, a1.z, a1.w};
            float bb[4] = {b0.x, b0.y, b0.z, b0.w};
            #pragma unroll
            for (int i = 0; i < 8; i++)
                #pragma unroll
                for (int j = 0; j < 4; j++)
                    acc[i][j] = fmaf(a[i], bb[j], acc[i][j]);
        }
        __syncthreads();
    }

    #pragma unroll
    for (int i = 0; i < 8; i++) {
        int m = bm + tidm * 8 + i;
        int n0 = bn + tidn * 4;
        float4 o;
        float* po = &o.x;
        #pragma unroll
        for (int j = 0; j < 4; j++) {
            int n = n0 + j;
            float v = acc[i][j] + bias[n];
            if (EPI) v = resid[(size_t)m * N + n] + gamma[n] * v;
            po[j] = v;
        }
        *(float4*)(Cout + (size_t)m * N + n0) = o;
    }
}

// ---------------- offsets (48) + attention logits (24) per query row ----------
// 8 query rows per block, warp w handles row w, all 72 outputs.
__global__ __launch_bounds__(256) void offaw_kernel(const float* __restrict__ qn,
                                                    const float* __restrict__ so_w,
                                                    const float* __restrict__ so_b,
                                                    const float* __restrict__ aw_w,
                                                    const float* __restrict__ aw_b,
                                                    float* __restrict__ out) {
    __shared__ float qs[8][C];
    int q0 = blockIdx.x * 8;
    int tid = threadIdx.x;
    for (int idx = tid; idx < 8 * C; idx += 256) {
        int r = idx / C, c = idx % C;
        qs[r][c] = qn[(size_t)(q0 + r) * C + c];
    }
    __syncthreads();

    int w = tid >> 5;
    int lane = tid & 31;
    const float* qrow = qs[w];

    for (int o = 0; o < 72; o++) {
        const float* wr = (o < 48) ? (so_w + (size_t)o * C) : (aw_w + (size_t)(o - 48) * C);
        float s0 = 0.f, s1 = 0.f;
        #pragma unroll
        for (int j = 0; j < 24; j += 2) {
            s0 = fmaf(qrow[lane + j * 32],       __ldg(&wr[lane + j * 32]),       s0);
            s1 = fmaf(qrow[lane + (j + 1) * 32], __ldg(&wr[lane + (j + 1) * 32]), s1);
        }
        float s = s0 + s1;
        #pragma unroll
        for (int off = 16; off; off >>= 1) s += __shfl_down_sync(0xffffffffu, s, off);
        if (lane == 0)
            out[(size_t)(q0 + w) * 72 + o] = s + ((o < 48) ? so_b[o] : aw_b[o - 48]);
    }
}

// ---------------- bilinear deformable sampling ----------------
__device__ __forceinline__ float fetchv(const float* __restrict__ val, int y, int x, int hd) {
    if ((unsigned)y < (unsigned)GRID && (unsigned)x < (unsigned)GRID)
        return __ldg(&val[(size_t)(y * GRID + x) * C + hd]);
    return 0.f;
}

__global__ __launch_bounds__(768) void sampler_kernel(const float* __restrict__ val,
                                                      const float* __restrict__ ref,
                                                      const float* __restrict__ oa,
                                                      float* __restrict__ out) {
    int q = blockIdx.x;
    int tid = threadIdx.x;
    __shared__ float s[72];
    if (tid < 72) s[tid] = oa[(size_t)q * 72 + tid];
    __syncthreads();

    int h = tid >> 7;       // head
    int hd = h * DH + (tid & 127);  // column in value
    float refx = ref[q * 2];
    float refy = ref[q * 2 + 1];

    // per-head softmax over 4 points (redundant across the 128 lanes of a head; cheap)
    float lg[4];
    #pragma unroll
    for (int p = 0; p < NP; p++) lg[p] = s[48 + h * 4 + p];
    float mx = fmaxf(fmaxf(lg[0], lg[1]), fmaxf(lg[2], lg[3]));
    float e[4];
    float se = 0.f;
    #pragma unroll
    for (int p = 0; p < NP; p++) { e[p] = __expf(lg[p] - mx); se += e[p]; }
    float inv = 1.f / se;

    float acc = 0.f;
    #pragma unroll
    for (int p = 0; p < NP; p++) {
        float px = refx * (float)GRID + s[(h * 4 + p) * 2]     - 0.5f;
        float py = refy * (float)GRID + s[(h * 4 + p) * 2 + 1] - 0.5f;
        float fx0 = floorf(px), fy0 = floorf(py);
        int x0 = (int)fx0, y0 = (int)fy0;
        float fx = px - fx0, fy = py - fy0;
        float w00 = (1.f - fy) * (1.f - fx);
        float w01 = (1.f - fy) * fx;
        float w10 = fy * (1.f - fx);
        float w11 = fy * fx;
        float v00 = fetchv(val, y0,     x0,     hd);
        float v01 = fetchv(val, y0,     x0 + 1, hd);
        float v10 = fetchv(val, y0 + 1, x0,     hd);
        float v11 = fetchv(val, y0 + 1, x0 + 1, hd);
        float samp = w00 * v00 + w01 * v01 + w10 * v10 + w11 * v11;
        acc = fmaf(e[p] * inv, samp, acc);
    }
    out[(size_t)q * C + tid] = acc;
}

// ---------------- host side ----------------
static void run_stage(const float* q_in, const float* feat, const float* ref,
                      const float* qn_w, const float* qn_b,
                      const float* fn_w, const float* fn_b,
                      const float* so_w, const float* so_b,
                      const float* aw_w, const float* aw_b,
                      const float* vp_w, const float* vp_b,
                      const float* op_w, const float* op_b,
                      const float* gamma, float* q_out,
                      float* s_qn, float* s_fn, float* s_val, float* s_oa, float* s_samp) {
    ln_kernel<<<LQ, 256>>>(q_in, qn_w, qn_b, s_qn);
    ln_kernel<<<LQ, 256>>>(feat, fn_w, fn_b, s_fn);
    gemm_tn<false><<<dim3(C / BN, LQ / BM), 256>>>(s_fn, vp_w, vp_b, nullptr, nullptr,
                                                   s_val, LQ, C, C);
    offaw_kernel<<<LQ / 8, 256>>>(s_qn, so_w, so_b, aw_w, aw_b, s_oa);
    sampler_kernel<<<LQ, 768>>>(s_val, ref, s_oa, s_samp);
    gemm_tn<true><<<dim3(C / BN, LQ / BM), 256>>>(s_samp, op_w, op_b, q_in, gamma,
                                                  q_out, LQ, C, C);
}

extern "C" void kernel_launch(void* const* d_in, const int* in_sizes, int n_in,
                              void* d_out, int out_size) {
    const float* query = (const float*)d_in[0];
    const float* ref   = (const float*)d_in[1];
    const float* feat  = (const float*)d_in[2];
    const float* feat2 = (const float*)d_in[3];
    // d_in[4] spatial_shapes (int64) and d_in[5] level_start_index unused: hardcoded 96x96, 1 level
    const float* qn_w = (const float*)d_in[6];
    const float* qn_b = (const float*)d_in[7];
    const float* fn_w = (const float*)d_in[8];
    const float* fn_b = (const float*)d_in[9];
    const float* so_w = (const float*)d_in[10];
    const float* so_b = (const float*)d_in[11];
    const float* aw_w = (const float*)d_in[12];
    const float* aw_b = (const float*)d_in[13];
    const float* vp_w = (const float*)d_in[14];
    const float* vp_b = (const float*)d_in[15];
    const float* op_w = (const float*)d_in[16];
    const float* op_b = (const float*)d_in[17];
    const float* gamma = (const float*)d_in[18];
    const float* qn2_w = (const float*)d_in[19];
    const float* qn2_b = (const float*)d_in[20];
    const float* fn2_w = (const float*)d_in[21];
    const float* fn2_b = (const float*)d_in[22];
    const float* so2_w = (const float*)d_in[23];
    const float* so2_b = (const float*)d_in[24];
    const float* aw2_w = (const float*)d_in[25];
    const float* aw2_b = (const float*)d_in[26];
    const float* vp2_w = (const float*)d_in[27];
    const float* vp2_b = (const float*)d_in[28];
    const float* op2_w = (const float*)d_in[29];
    const float* op2_b = (const float*)d_in[30];
    const float* gamma2 = (const float*)d_in[31];
    float* out = (float*)d_out;

    float *p_qn, *p_fn, *p_val, *p_samp, *p_q1, *p_oa;
    cudaGetSymbolAddress((void**)&p_qn, g_qn);
    cudaGetSymbolAddress((void**)&p_fn, g_fn);
    cudaGetSymbolAddress((void**)&p_val, g_val);
    cudaGetSymbolAddress((void**)&p_samp, g_samp);
    cudaGetSymbolAddress((void**)&p_q1, g_q1);
    cudaGetSymbolAddress((void**)&p_oa, g_oa);

    // Stage 1: q1 = query + gamma * MSDeform(LN(query), ref, LN(feat))
    run_stage(query, feat, ref,
              qn_w, qn_b, fn_w, fn_b, so_w, so_b, aw_w, aw_b,
              vp_w, vp_b, op_w, op_b, gamma, p_q1,
              p_qn, p_fn, p_val, p_oa, p_samp);

    // Stage 2: out = q1 + gamma2 * MSDeform(LN(q1), ref, LN(feat_other))
    run_stage(p_q1, feat2, ref,
              qn2_w, qn2_b, fn2_w, fn2_b, so2_w, so2_b, aw2_w, aw2_b,
              vp2_w, vp2_b, op2_w, op2_b, gamma2, out,
              p_qn, p_fn, p_val, p_oa, p_samp);
}

// round 2
// speedup vs baseline: 3.3376x; 3.3376x over previous
#include <cuda_runtime.h>
#include <cuda_bf16.h>
#include <cstdint>

#define LQ 9216
#define C 768
#define NH 6
#define DH 128
#define NP 4
#define GRID 96
#define NOA 128   // padded offset+aw output width (48 offs + 24 logits + 56 pad)

// ---------------- scratch (no allocations allowed) ----------------
__device__ __nv_bfloat16 s_qn[LQ * C];
__device__ __nv_bfloat16 s_fn[LQ * C];
__device__ __nv_bfloat16 s_samp[LQ * C];
__device__ __nv_bfloat16 w_vp[2][C * C];
__device__ __nv_bfloat16 w_op[2][C * C];
__device__ __nv_bfloat16 w_oa[2][NOA * C];
__device__ float b_oa[2][NOA];
__device__ float g_val[LQ * C];
__device__ float g_q1[LQ * C];
__device__ float g_oa[LQ * NOA];

// ---------------- weight conversion ----------------
__global__ void cvt_bf16(const float* __restrict__ src, __nv_bfloat16* __restrict__ dst, int n) {
    int i = blockIdx.x * 256 + threadIdx.x;
    if (i < n) dst[i] = __float2bfloat16(src[i]);
}

__global__ void pack_oa_kernel(const float* __restrict__ so_w, const float* __restrict__ aw_w,
                               const float* __restrict__ so_b, const float* __restrict__ aw_b,
                               __nv_bfloat16* __restrict__ w, float* __restrict__ b) {
    int i = blockIdx.x * 256 + threadIdx.x;
    if (i < NOA * C) {
        float v = 0.f;
        if (i < 48 * C) v = so_w[i];
        else if (i < 72 * C) v = aw_w[i - 48 * C];
        w[i] = __float2bfloat16(v);
    }
    if (i < NOA) b[i] = (i < 48) ? so_b[i] : (i < 72 ? aw_b[i - 48] : 0.f);
}

// ---------------- LayerNorm -> bf16, 192 threads (float4 per thread) ----------
__global__ __launch_bounds__(192) void ln_bf16(const float* __restrict__ x,
                                               const float* __restrict__ w,
                                               const float* __restrict__ b,
                                               __nv_bfloat16* __restrict__ y) {
    int row = blockIdx.x;
    int t = threadIdx.x;
    int lane = t & 31, wid = t >> 5;
    float4 v = ((const float4*)(x + (size_t)row * C))[t];

    __shared__ float part[6];
    float s = v.x + v.y + v.z + v.w;
    #pragma unroll
    for (int o = 16; o; o >>= 1) s += __shfl_down_sync(0xffffffffu, s, o);
    if (!lane) part[wid] = s;
    __syncthreads();
    float mu = (part[0] + part[1] + part[2] + part[3] + part[4] + part[5]) * (1.f / C);

    float dx = v.x - mu, dy = v.y - mu, dz = v.z - mu, dw = v.w - mu;
    s = dx * dx + dy * dy + dz * dz + dw * dw;
    __syncthreads();
    #pragma unroll
    for (int o = 16; o; o >>= 1) s += __shfl_down_sync(0xffffffffu, s, o);
    if (!lane) part[wid] = s;
    __syncthreads();
    float rs = rsqrtf((part[0] + part[1] + part[2] + part[3] + part[4] + part[5]) * (1.f / C) + 1e-6f);

    float4 wv = ((const float4*)w)[t];
    float4 bv = ((const float4*)b)[t];
    __nv_bfloat162 p0 = __floats2bfloat162_rn(dx * rs * wv.x + bv.x, dy * rs * wv.y + bv.y);
    __nv_bfloat162 p1 = __floats2bfloat162_rn(dz * rs * wv.z + bv.z, dw * rs * wv.w + bv.w);
    __nv_bfloat162* yr = (__nv_bfloat162*)(y + (size_t)row * C);
    yr[t * 2] = p0;
    yr[t * 2 + 1] = p1;
}

// ---------------- bf16 HMMA GEMM: C[m,n] = A[m,:]·B[n,:] + bias[n] ----------
// MODE 0: out = acc + bias ; MODE 1: out = resid + gamma*(acc+bias)
#define GBM 128
#define GBN 64
#define GBK 32
#define LDA 40   // GBK + 8 pad (80B row stride: 16B-aligned, ldmatrix conflict-free)

__device__ __forceinline__ void mma16816(float* c, const uint32_t* a, const uint32_t* b) {
    asm volatile(
        "mma.sync.aligned.m16n8k16.row.col.f32.bf16.bf16.f32 "
        "{%0,%1,%2,%3}, {%4,%5,%6,%7}, {%8,%9}, {%0,%1,%2,%3};\n"
        : "+f"(c[0]), "+f"(c[1]), "+f"(c[2]), "+f"(c[3])
        : "r"(a[0]), "r"(a[1]), "r"(a[2]), "r"(a[3]), "r"(b[0]), "r"(b[1]));
}

template <int MODE>
__global__ __launch_bounds__(256) void gemm_bf16(const __nv_bfloat16* __restrict__ A,
                                                 const __nv_bfloat16* __restrict__ B,
                                                 const float* __restrict__ bias,
                                                 const float* __restrict__ resid,
                                                 const float* __restrict__ gamma,
                                                 float* __restrict__ Cout,
                                                 int M, int N, int K) {
    __shared__ __nv_bfloat16 As[GBM][LDA];
    __shared__ __nv_bfloat16 Bs[GBN][LDA];

    int tid = threadIdx.x;
    int warp = tid >> 5, lane = tid & 31;
    int bm = blockIdx.y * GBM, bn = blockIdx.x * GBN;
    int wm = (warp >> 1) * 32;   // 4 warps along m
    int wn = (warp & 1) * 32;    // 2 warps along n

    float acc[2][4][4] = {};

    uint32_t a_addr[2][2], b_addr[4][2];
    #pragma unroll
    for (int ma = 0; ma < 2; ma++)
        #pragma unroll
        for (int ks = 0; ks < 2; ks++)
            a_addr[ma][ks] = (uint32_t)__cvta_generic_to_shared(
                &As[wm + ma * 16 + (lane & 15)][ks * 16 + (lane >> 4) * 8]);
    #pragma unroll
    for (int na = 0; na < 4; na++)
        #pragma unroll
        for (int ks = 0; ks < 2; ks++)
            b_addr[na][ks] = (uint32_t)__cvta_generic_to_shared(
                &Bs[wn + na * 8 + (lane & 7)][ks * 16 + ((lane >> 3) & 1) * 8]);

    for (int k0 = 0; k0 < K; k0 += GBK) {
        #pragma unroll
        for (int i = 0; i < 2; i++) {
            int c = tid + i * 256;
            int r = c >> 2, kc = (c & 3) << 3;
            uint4 v = *(const uint4*)(A + (size_t)(bm + r) * K + k0 + kc);
            *(uint4*)&As[r][kc] = v;
        }
        {
            int r = tid >> 2, kc = (tid & 3) << 3;
            uint4 v = *(const uint4*)(B + (size_t)(bn + r) * K + k0 + kc);
            *(uint4*)&Bs[r][kc] = v;
        }
        __syncthreads();

        #pragma unroll
        for (int ks = 0; ks < 2; ks++) {
            uint32_t af[2][4], bf[4][2];
            #pragma unroll
            for (int ma = 0; ma < 2; ma++)
                asm volatile("ldmatrix.sync.aligned.m8n8.x4.shared.b16 {%0,%1,%2,%3}, [%4];"
                             : "=r"(af[ma][0]), "=r"(af[ma][1]), "=r"(af[ma][2]), "=r"(af[ma][3])
                             : "r"(a_addr[ma][ks]));
            #pragma unroll
            for (int na = 0; na < 4; na++)
                asm volatile("ldmatrix.sync.aligned.m8n8.x2.shared.b16 {%0,%1}, [%2];"
                             : "=r"(bf[na][0]), "=r"(bf[na][1])
                             : "r"(b_addr[na][ks]));
            #pragma unroll
            for (int ma = 0; ma < 2; ma++)
                #pragma unroll
                for (int na = 0; na < 4; na++)
                    mma16816(acc[ma][na], af[ma], bf[na]);
        }
        __syncthreads();
    }

    int tr = lane >> 2, tc = (lane & 3) * 2;
    #pragma unroll
    for (int ma = 0; ma < 2; ma++) {
        #pragma unroll
        for (int half = 0; half < 2; half++) {
            int m = bm + wm + ma * 16 + tr + half * 8;
            #pragma unroll
            for (int na = 0; na < 4; na++) {
                int n = bn + wn + na * 8 + tc;
                float v0 = acc[ma][na][half * 2 + 0] + bias[n];
                float v1 = acc[ma][na][half * 2 + 1] + bias[n + 1];
                if (MODE == 1) {
                    v0 = resid[(size_t)m * N + n] + gamma[n] * v0;
                    v1 = resid[(size_t)m * N + n + 1] + gamma[n + 1] * v1;
                }
                *(float2*)(Cout + (size_t)m * N + n) = make_float2(v0, v1);
            }
        }
    }
}

// ---------------- bilinear deformable sampling (value fp32 -> samp bf16) ------
__device__ __forceinline__ float fetchv(const float* __restrict__ val, int y, int x, int hd) {
    if ((unsigned)y < (unsigned)GRID && (unsigned)x < (unsigned)GRID)
        return __ldg(&val[(size_t)(y * GRID + x) * C + hd]);
    return 0.f;
}

__global__ __launch_bounds__(768) void sampler_kernel(const float* __restrict__ val,
                                                      const float* __restrict__ ref,
                                                      const float* __restrict__ oa,
                                                      __nv_bfloat16* __restrict__ out) {
    int q = blockIdx.x;
    int tid = threadIdx.x;
    __shared__ float s[72];
    if (tid < 72) s[tid] = oa[(size_t)q * NOA + tid];
    __syncthreads();

    int h = tid >> 7;
    int hd = tid;  // h*128 + (tid&127)
    float refx = ref[q * 2];
    float refy = ref[q * 2 + 1];

    float lg[4];
    #pragma unroll
    for (int p = 0; p < NP; p++) lg[p] = s[48 + h * 4 + p];
    float mx = fmaxf(fmaxf(lg[0], lg[1]), fmaxf(lg[2], lg[3]));
    float e[4];
    float se = 0.f;
    #pragma unroll
    for (int p = 0; p < NP; p++) { e[p] = __expf(lg[p] - mx); se += e[p]; }
    float inv = 1.f / se;

    float acc = 0.f;
    #pragma unroll
    for (int p = 0; p < NP; p++) {
        float px = refx * (float)GRID + s[(h * 4 + p) * 2]     - 0.5f;
        float py = refy * (float)GRID + s[(h * 4 + p) * 2 + 1] - 0.5f;
        float fx0 = floorf(px), fy0 = floorf(py);
        int x0 = (int)fx0, y0 = (int)fy0;
        float fx = px - fx0, fy = py - fy0;
        float w00 = (1.f - fy) * (1.f - fx);
        float w01 = (1.f - fy) * fx;
        float w10 = fy * (1.f - fx);
        float w11 = fy * fx;
        float v00 = fetchv(val, y0,     x0,     hd);
        float v01 = fetchv(val, y0,     x0 + 1, hd);
        float v10 = fetchv(val, y0 + 1, x0,     hd);
        float v11 = fetchv(val, y0 + 1, x0 + 1, hd);
        float samp = w00 * v00 + w01 * v01 + w10 * v10 + w11 * v11;
        acc = fmaf(e[p] * inv, samp, acc);
    }
    out[(size_t)q * C + tid] = __float2bfloat16(acc);
}

// ---------------- host side ----------------
static void run_stage(const float* q_in, const float* feat, const float* ref,
                      const float* qn_w, const float* qn_b,
                      const float* fn_w, const float* fn_b,
                      const float* vp_b, const float* op_b,
                      const float* gamma, float* q_out,
                      __nv_bfloat16* p_qn, __nv_bfloat16* p_fn, __nv_bfloat16* p_samp,
                      const __nv_bfloat16* pw_vp, const __nv_bfloat16* pw_op,
                      const __nv_bfloat16* pw_oa, const float* pb_oa,
                      float* p_val, float* p_oa) {
    ln_bf16<<<LQ, 192>>>(q_in, qn_w, qn_b, p_qn);
    ln_bf16<<<LQ, 192>>>(feat, fn_w, fn_b, p_fn);
    gemm_bf16<0><<<dim3(C / GBN, LQ / GBM), 256>>>(p_fn, pw_vp, vp_b, nullptr, nullptr,
                                                   p_val, LQ, C, C);
    gemm_bf16<0><<<dim3(NOA / GBN, LQ / GBM), 256>>>(p_qn, pw_oa, pb_oa, nullptr, nullptr,
                                                     p_oa, LQ, NOA, C);
    sampler_kernel<<<LQ, 768>>>(p_val, ref, p_oa, p_samp);
    gemm_bf16<1><<<dim3(C / GBN, LQ / GBM), 256>>>(p_samp, pw_op, op_b, q_in, gamma,
                                                   q_out, LQ, C, C);
}

extern "C" void kernel_launch(void* const* d_in, const int* in_sizes, int n_in,
                              void* d_out, int out_size) {
    const float* query = (const float*)d_in[0];
    const float* ref   = (const float*)d_in[1];
    const float* feat  = (const float*)d_in[2];
    const float* feat2 = (const float*)d_in[3];
    const float* qn_w = (const float*)d_in[6];
    const float* qn_b = (const float*)d_in[7];
    const float* fn_w = (const float*)d_in[8];
    const float* fn_b = (const float*)d_in[9];
    const float* so_w = (const float*)d_in[10];
    const float* so_b = (const float*)d_in[11];
    const float* aw_w = (const float*)d_in[12];
    const float* aw_b = (const float*)d_in[13];
    const float* vp_w = (const float*)d_in[14];
    const float* vp_b = (const float*)d_in[15];
    const float* op_w = (const float*)d_in[16];
    const float* op_b = (const float*)d_in[17];
    const float* gamma = (const float*)d_in[18];
    const float* qn2_w = (const float*)d_in[19];
    const float* qn2_b = (const float*)d_in[20];
    const float* fn2_w = (const float*)d_in[21];
    const float* fn2_b = (const float*)d_in[22];
    const float* so2_w = (const float*)d_in[23];
    const float* so2_b = (const float*)d_in[24];
    const float* aw2_w = (const float*)d_in[25];
    const float* aw2_b = (const float*)d_in[26];
    const float* vp2_w = (const float*)d_in[27];
    const float* vp2_b = (const float*)d_in[28];
    const float* op2_w = (const float*)d_in[29];
    const float* op2_b = (const float*)d_in[30];
    const float* gamma2 = (const float*)d_in[31];
    float* out = (float*)d_out;

    __nv_bfloat16 *p_qn, *p_fn, *p_samp, *pw_vp, *pw_op, *pw_oa;
    float *p_val, *p_q1, *p_oa, *pb_oa;
    cudaGetSymbolAddress((void**)&p_qn, s_qn);
    cudaGetSymbolAddress((void**)&p_fn, s_fn);
    cudaGetSymbolAddress((void**)&p_samp, s_samp);
    cudaGetSymbolAddress((void**)&pw_vp, w_vp);
    cudaGetSymbolAddress((void**)&pw_op, w_op);
    cudaGetSymbolAddress((void**)&pw_oa, w_oa);
    cudaGetSymbolAddress((void**)&pb_oa, b_oa);
    cudaGetSymbolAddress((void**)&p_val, g_val);
    cudaGetSymbolAddress((void**)&p_q1, g_q1);
    cudaGetSymbolAddress((void**)&p_oa, g_oa);

    int nW = C * C;
    cvt_bf16<<<(nW + 255) / 256, 256>>>(vp_w, pw_vp, nW);
    cvt_bf16<<<(nW + 255) / 256, 256>>>(op_w, pw_op, nW);
    cvt_bf16<<<(nW + 255) / 256, 256>>>(vp2_w, pw_vp + nW, nW);
    cvt_bf16<<<(nW + 255) / 256, 256>>>(op2_w, pw_op + nW, nW);
    pack_oa_kernel<<<(NOA * C + 255) / 256, 256>>>(so_w, aw_w, so_b, aw_b, pw_oa, pb_oa);
    pack_oa_kernel<<<(NOA * C + 255) / 256, 256>>>(so2_w, aw2_w, so2_b, aw2_b,
                                                   pw_oa + NOA * C, pb_oa + NOA);

    // Stage 1: q1 = query + gamma * MSDeform(LN(query), ref, LN(feat))
    run_stage(query, feat, ref, qn_w, qn_b, fn_w, fn_b, vp_b, op_b, gamma, p_q1,
              p_qn, p_fn, p_samp, pw_vp, pw_op, pw_oa, pb_oa, p_val, p_oa);

    // Stage 2: out = q1 + gamma2 * MSDeform(LN(q1), ref, LN(feat2))
    run_stage(p_q1, feat2, ref, qn2_w, qn2_b, fn2_w, fn2_b, vp2_b, op2_b, gamma2, out,
              p_qn, p_fn, p_samp, pw_vp + nW, pw_op + nW, pw_oa + NOA * C, pb_oa + NOA,
              p_val, p_oa);
}

// round 8
// speedup vs baseline: 3.8487x; 1.1531x over previous
#include <cuda_runtime.h>
#include <cuda_bf16.h>
#include <cstdint>

#define LQ 9216
#define C 768
#define NH 6
#define DH 128
#define NP 4
#define GRID 96
#define NOA 128   // padded offset+aw output width (48 offs + 24 logits + 56 pad)

// ---------------- scratch (no allocations allowed) ----------------
__device__ __nv_bfloat16 s_qn[LQ * C];
__device__ __nv_bfloat16 s_fn[LQ * C];
__device__ __nv_bfloat16 s_samp[LQ * C];
__device__ __nv_bfloat16 s_val[LQ * C];
__device__ __nv_bfloat16 w_vp[2][C * C];
__device__ __nv_bfloat16 w_op[2][C * C];
__device__ __nv_bfloat16 w_oa[2][NOA * C];
__device__ float b_oa[2][NOA];
__device__ float g_q1[LQ * C];
__device__ float g_oa[LQ * NOA];

// ---------------- fused weight prep (1 launch) ----------------
__global__ void prep_weights(const float* __restrict__ vp1, const float* __restrict__ op1,
                             const float* __restrict__ vp2, const float* __restrict__ op2,
                             const float* __restrict__ so1, const float* __restrict__ aw1,
                             const float* __restrict__ so1b, const float* __restrict__ aw1b,
                             const float* __restrict__ so2, const float* __restrict__ aw2,
                             const float* __restrict__ so2b, const float* __restrict__ aw2b,
                             __nv_bfloat16* __restrict__ wvp, __nv_bfloat16* __restrict__ wop,
                             __nv_bfloat16* __restrict__ woa, float* __restrict__ boa) {
    int i = blockIdx.x * 256 + threadIdx.x;
    const int nW = C * C;
    if (i < nW) {
        wvp[i] = __float2bfloat16(vp1[i]);
        wop[i] = __float2bfloat16(op1[i]);
        wvp[nW + i] = __float2bfloat16(vp2[i]);
        wop[nW + i] = __float2bfloat16(op2[i]);
    }
    if (i < NOA * C) {
        float v1 = 0.f, v2 = 0.f;
        if (i < 48 * C) { v1 = so1[i]; v2 = so2[i]; }
        else if (i < 72 * C) { v1 = aw1[i - 48 * C]; v2 = aw2[i - 48 * C]; }
        woa[i] = __float2bfloat16(v1);
        woa[NOA * C + i] = __float2bfloat16(v2);
    }
    if (i < NOA) {
        boa[i]       = (i < 48) ? so1b[i] : (i < 72 ? aw1b[i - 48] : 0.f);
        boa[NOA + i] = (i < 48) ? so2b[i] : (i < 72 ? aw2b[i - 48] : 0.f);
    }
}

// ---------------- dual LayerNorm -> bf16 (2 tensors in one launch) ----------
__global__ __launch_bounds__(192) void ln_dual(const float* __restrict__ xa,
                                               const float* __restrict__ wa,
                                               const float* __restrict__ ba,
                                               __nv_bfloat16* __restrict__ ya,
                                               const float* __restrict__ xb,
                                               const float* __restrict__ wb,
                                               const float* __restrict__ bb,
                                               __nv_bfloat16* __restrict__ yb) {
    int row = blockIdx.x;
    const float *x, *w, *b;
    __nv_bfloat16* y;
    if (row < LQ) { x = xa; w = wa; b = ba; y = ya; }
    else { row -= LQ; x = xb; w = wb; b = bb; y = yb; }

    int t = threadIdx.x;
    int lane = t & 31, wid = t >> 5;
    float4 v = ((const float4*)(x + (size_t)row * C))[t];

    __shared__ float part[6];
    float s = v.x + v.y + v.z + v.w;
    #pragma unroll
    for (int o = 16; o; o >>= 1) s += __shfl_down_sync(0xffffffffu, s, o);
    if (!lane) part[wid] = s;
    __syncthreads();
    float mu = (part[0] + part[1] + part[2] + part[3] + part[4] + part[5]) * (1.f / C);

    float dx = v.x - mu, dy = v.y - mu, dz = v.z - mu, dw = v.w - mu;
    s = dx * dx + dy * dy + dz * dz + dw * dw;
    __syncthreads();
    #pragma unroll
    for (int o = 16; o; o >>= 1) s += __shfl_down_sync(0xffffffffu, s, o);
    if (!lane) part[wid] = s;
    __syncthreads();
    float rs = rsqrtf((part[0] + part[1] + part[2] + part[3] + part[4] + part[5]) * (1.f / C) + 1e-6f);

    float4 wv = ((const float4*)w)[t];
    float4 bv = ((const float4*)b)[t];
    __nv_bfloat162 p0 = __floats2bfloat162_rn(dx * rs * wv.x + bv.x, dy * rs * wv.y + bv.y);
    __nv_bfloat162 p1 = __floats2bfloat162_rn(dz * rs * wv.z + bv.z, dw * rs * wv.w + bv.w);
    __nv_bfloat162* yr = (__nv_bfloat162*)(y + (size_t)row * C);
    yr[t * 2] = p0;
    yr[t * 2 + 1] = p1;
}

// ---------------- bf16 HMMA GEMM, 128x128x32, double-buffered cp.async -------
#define GBM 128
#define GBN 128
#define GBK 32
#define LDA 40   // elements; 80B row stride (16B aligned, reduces conflicts)

__device__ __forceinline__ void mma16816(float* c, const uint32_t* a, const uint32_t* b) {
    asm volatile(
        "mma.sync.aligned.m16n8k16.row.col.f32.bf16.bf16.f32 "
        "{%0,%1,%2,%3}, {%4,%5,%6,%7}, {%8,%9}, {%0,%1,%2,%3};\n"
        : "+f"(c[0]), "+f"(c[1]), "+f"(c[2]), "+f"(c[3])
        : "r"(a[0]), "r"(a[1]), "r"(a[2]), "r"(a[3]), "r"(b[0]), "r"(b[1]));
}

__device__ __forceinline__ void cp16(uint32_t s, const void* g) {
    asm volatile("cp.async.cg.shared.global [%0], [%1], 16;\n" :: "r"(s), "l"(g));
}

// MODE 0: out = acc + bias ; MODE 1: out = resid + gamma*(acc+bias)
// OUT_BF16: store bf16 instead of float
template <int MODE, bool OUT_BF16>
__global__ __launch_bounds__(256) void gemm_bf16(const __nv_bfloat16* __restrict__ A,
                                                 const __nv_bfloat16* __restrict__ B,
                                                 const float* __restrict__ bias,
                                                 const float* __restrict__ resid,
                                                 const float* __restrict__ gamma,
                                                 void* __restrict__ Cout,
                                                 int M, int N, int K) {
    __shared__ __nv_bfloat16 As[2][GBM][LDA];
    __shared__ __nv_bfloat16 Bs[2][GBN][LDA];
    const uint32_t ASTG = GBM * LDA * 2;   // stage stride bytes
    const uint32_t BSTG = GBN * LDA * 2;

    int tid = threadIdx.x;
    int warp = tid >> 5, lane = tid & 31;
    int bm = blockIdx.y * GBM, bn = blockIdx.x * GBN;
    int wm = (warp >> 1) * 32;   // 4 warps along m (32 rows each)
    int wn = (warp & 1) * 64;    // 2 warps along n (64 cols each)

    uint32_t sA = (uint32_t)__cvta_generic_to_shared(&As[0][0][0]);
    uint32_t sB = (uint32_t)__cvta_generic_to_shared(&Bs[0][0][0]);

    // cp.async thread mapping: idx -> row idx>>2, 8-elem chunk (idx&3)*8
    int ldr = tid >> 2, ldc = (tid & 3) * 8;
    uint32_t a_dst = sA + ldr * (LDA * 2) + ldc * 2;
    uint32_t b_dst = sB + ldr * (LDA * 2) + ldc * 2;
    int ldr2 = (tid + 256) >> 2;
    uint32_t a_dst2 = sA + ldr2 * (LDA * 2) + ldc * 2;
    uint32_t b_dst2 = sB + ldr2 * (LDA * 2) + ldc * 2;

    // ldmatrix fragment addresses (stage 0)
    uint32_t a_addr[2][2], b_addr[4][2];
    #pragma unroll
    for (int ma = 0; ma < 2; ma++)
        #pragma unroll
        for (int ks = 0; ks < 2; ks++)
            a_addr[ma][ks] = (uint32_t)__cvta_generic_to_shared(
                &As[0][wm + ma * 16 + (lane & 15)][ks * 16 + (lane >> 4) * 8]);
    #pragma unroll
    for (int pr = 0; pr < 4; pr++)
        #pragma unroll
        for (int ks = 0; ks < 2; ks++)
            b_addr[pr][ks] = (uint32_t)__cvta_generic_to_shared(
                &Bs[0][wn + pr * 16 + (lane & 15)][ks * 16 + (lane >> 4) * 8]);

    float acc[2][8][4] = {};

    const int NK = K / GBK;
    // prologue: stage 0
    {
        const __nv_bfloat16* Ab = A + (size_t)bm * K;
        const __nv_bfloat16* Bb = B + (size_t)bn * K;
        cp16(a_dst, Ab + (size_t)ldr * K + ldc);
        cp16(a_dst2, Ab + (size_t)ldr2 * K + ldc);
        cp16(b_dst, Bb + (size_t)ldr * K + ldc);
        cp16(b_dst2, Bb + (size_t)ldr2 * K + ldc);
        asm volatile("cp.async.commit_group;\n");
    }

    int buf = 0;
    for (int it = 0; it < NK; it++) {
        if (it + 1 < NK) {
            int k0 = (it + 1) * GBK;
            uint32_t off = (buf ^ 1) ? 1u : 0u;
            const __nv_bfloat16* Ab = A + (size_t)bm * K + k0;
            const __nv_bfloat16* Bb = B + (size_t)bn * K + k0;
            cp16(a_dst + off * ASTG, Ab + (size_t)ldr * K + ldc);
            cp16(a_dst2 + off * ASTG, Ab + (size_t)ldr2 * K + ldc);
            cp16(b_dst + off * BSTG, Bb + (size_t)ldr * K + ldc);
            cp16(b_dst2 + off * BSTG, Bb + (size_t)ldr2 * K + ldc);
            asm volatile("cp.async.commit_group;\n");
            asm volatile("cp.async.wait_group 1;\n");
        } else {
            asm volatile("cp.async.wait_group 0;\n");
        }
        __syncthreads();

        uint32_t aoff = buf ? ASTG : 0u;
        uint32_t boff = buf ? BSTG : 0u;
        #pragma unroll
        for (int ks = 0; ks < 2; ks++) {
            uint32_t af[2][4], bf[8][2];
            #pragma unroll
            for (int ma = 0; ma < 2; ma++)
                asm volatile("ldmatrix.sync.aligned.m8n8.x4.shared.b16 {%0,%1,%2,%3}, [%4];"
                             : "=r"(af[ma][0]), "=r"(af[ma][1]), "=r"(af[ma][2]), "=r"(af[ma][3])
                             : "r"(a_addr[ma][ks] + aoff));
            #pragma unroll
            for (int pr = 0; pr < 4; pr++) {
                uint32_t r0, r1, r2, r3;
                asm volatile("ldmatrix.sync.aligned.m8n8.x4.shared.b16 {%0,%1,%2,%3}, [%4];"
                             : "=r"(r0), "=r"(r1), "=r"(r2), "=r"(r3)
                             : "r"(b_addr[pr][ks] + boff));
                bf[pr * 2 + 0][0] = r0; bf[pr * 2 + 0][1] = r2;
                bf[pr * 2 + 1][0] = r1; bf[pr * 2 + 1][1] = r3;
            }
            #pragma unroll
            for (int ma = 0; ma < 2; ma++)
                #pragma unroll
                for (int na = 0; na < 8; na++)
                    mma16816(acc[ma][na], af[ma], bf[na]);
        }
        __syncthreads();
        buf ^= 1;
    }

    int tr = lane >> 2, tc = (lane & 3) * 2;
    #pragma unroll
    for (int ma = 0; ma < 2; ma++) {
        #pragma unroll
        for (int half = 0; half < 2; half++) {
            int m = bm + wm + ma * 16 + half * 8 + tr;
            #pragma unroll
            for (int na = 0; na < 8; na++) {
                int n = bn + wn + na * 8 + tc;
                float v0 = acc[ma][na][half * 2 + 0] + bias[n];
                float v1 = acc[ma][na][half * 2 + 1] + bias[n + 1];
                if (MODE == 1) {
                    v0 = resid[(size_t)m * N + n] + gamma[n] * v0;
                    v1 = resid[(size_t)m * N + n + 1] + gamma[n + 1] * v1;
                }
                if (OUT_BF16)
                    *(__nv_bfloat162*)((__nv_bfloat16*)Cout + (size_t)m * N + n) =
                        __floats2bfloat162_rn(v0, v1);
                else
                    *(float2*)((float*)Cout + (size_t)m * N + n) = make_float2(v0, v1);
            }
        }
    }
}

// ---------------- bilinear deformable sampling (bf16 value) ----------------
__device__ __forceinline__ float fetchv(const __nv_bfloat16* __restrict__ val, int y, int x, int hd) {
    if ((unsigned)y < (unsigned)GRID && (unsigned)x < (unsigned)GRID)
        return __bfloat162float(__ldg(&val[(size_t)(y * GRID + x) * C + hd]));
    return 0.f;
}

__global__ __launch_bounds__(768) void sampler_kernel(const __nv_bfloat16* __restrict__ val,
                                                      const float* __restrict__ ref,
                                                      const float* __restrict__ oa,
                                                      __nv_bfloat16* __restrict__ out) {
    int q = blockIdx.x;
    int tid = threadIdx.x;
    __shared__ float s[72];
    if (tid < 72) s[tid] = oa[(size_t)q * NOA + tid];
    __syncthreads();

    int h = tid >> 7;
    int hd = tid;
    float refx = ref[q * 2];
    float refy = ref[q * 2 + 1];

    float lg[4];
    #pragma unroll
    for (int p = 0; p < NP; p++) lg[p] = s[48 + h * 4 + p];
    float mx = fmaxf(fmaxf(lg[0], lg[1]), fmaxf(lg[2], lg[3]));
    float e[4];
    float se = 0.f;
    #pragma unroll
    for (int p = 0; p < NP; p++) { e[p] = __expf(lg[p] - mx); se += e[p]; }
    float inv = 1.f / se;

    float acc = 0.f;
    #pragma unroll
    for (int p = 0; p < NP; p++) {
        float px = refx * (float)GRID + s[(h * 4 + p) * 2]     - 0.5f;
        float py = refy * (float)GRID + s[(h * 4 + p) * 2 + 1] - 0.5f;
        float fx0 = floorf(px), fy0 = floorf(py);
        int x0 = (int)fx0, y0 = (int)fy0;
        float fx = px - fx0, fy = py - fy0;
        float w00 = (1.f - fy) * (1.f - fx);
        float w01 = (1.f - fy) * fx;
        float w10 = fy * (1.f - fx);
        float w11 = fy * fx;
        float v00 = fetchv(val, y0,     x0,     hd);
        float v01 = fetchv(val, y0,     x0 + 1, hd);
        float v10 = fetchv(val, y0 + 1, x0,     hd);
        float v11 = fetchv(val, y0 + 1, x0 + 1, hd);
        float samp = w00 * v00 + w01 * v01 + w10 * v10 + w11 * v11;
        acc = fmaf(e[p] * inv, samp, acc);
    }
    out[(size_t)q * C + tid] = __float2bfloat16(acc);
}

// ---------------- host side ----------------
static void run_stage(const float* q_in, const float* feat, const float* ref,
                      const float* qn_w, const float* qn_b,
                      const float* fn_w, const float* fn_b,
                      const float* vp_b, const float* op_b,
                      const float* gamma, float* q_out,
                      __nv_bfloat16* p_qn, __nv_bfloat16* p_fn, __nv_bfloat16* p_samp,
                      __nv_bfloat16* p_val,
                      const __nv_bfloat16* pw_vp, const __nv_bfloat16* pw_op,
                      const __nv_bfloat16* pw_oa, const float* pb_oa,
                      float* p_oa) {
    ln_dual<<<2 * LQ, 192>>>(q_in, qn_w, qn_b, p_qn, feat, fn_w, fn_b, p_fn);
    gemm_bf16<0, true><<<dim3(C / GBN, LQ / GBM), 256>>>(p_fn, pw_vp, vp_b, nullptr, nullptr,
                                                         p_val, LQ, C, C);
    gemm_bf16<0, false><<<dim3(1, LQ / GBM), 256>>>(p_qn, pw_oa, pb_oa, nullptr, nullptr,
                                                    p_oa, LQ, NOA, C);
    sampler_kernel<<<LQ, 768>>>(p_val, ref, p_oa, p_samp);
    gemm_bf16<1, false><<<dim3(C / GBN, LQ / GBM), 256>>>(p_samp, pw_op, op_b, q_in, gamma,
                                                          q_out, LQ, C, C);
}

extern "C" void kernel_launch(void* const* d_in, const int* in_sizes, int n_in,
                              void* d_out, int out_size) {
    const float* query = (const float*)d_in[0];
    const float* ref   = (const float*)d_in[1];
    const float* feat  = (const float*)d_in[2];
    const float* feat2 = (const float*)d_in[3];
    const float* qn_w = (const float*)d_in[6];
    const float* qn_b = (const float*)d_in[7];
    const float* fn_w = (const float*)d_in[8];
    const float* fn_b = (const float*)d_in[9];
    const float* so_w = (const float*)d_in[10];
    const float* so_b = (const float*)d_in[11];
    const float* aw_w = (const float*)d_in[12];
    const float* aw_b = (const float*)d_in[13];
    const float* vp_w = (const float*)d_in[14];
    const float* vp_b = (const float*)d_in[15];
    const float* op_w = (const float*)d_in[16];
    const float* op_b = (const float*)d_in[17];
    const float* gamma = (const float*)d_in[18];
    const float* qn2_w = (const float*)d_in[19];
    const float* qn2_b = (const float*)d_in[20];
    const float* fn2_w = (const float*)d_in[21];
    const float* fn2_b = (const float*)d_in[22];
    const float* so2_w = (const float*)d_in[23];
    const float* so2_b = (const float*)d_in[24];
    const float* aw2_w = (const float*)d_in[25];
    const float* aw2_b = (const float*)d_in[26];
    const float* vp2_w = (const float*)d_in[27];
    const float* vp2_b = (const float*)d_in[28];
    const float* op2_w = (const float*)d_in[29];
    const float* op2_b = (const float*)d_in[30];
    const float* gamma2 = (const float*)d_in[31];
    float* out = (float*)d_out;

    __nv_bfloat16 *p_qn, *p_fn, *p_samp, *p_val, *pw_vp, *pw_op, *pw_oa;
    float *p_q1, *p_oa, *pb_oa;
    cudaGetSymbolAddress((void**)&p_qn, s_qn);
    cudaGetSymbolAddress((void**)&p_fn, s_fn);
    cudaGetSymbolAddress((void**)&p_samp, s_samp);
    cudaGetSymbolAddress((void**)&p_val, s_val);
    cudaGetSymbolAddress((void**)&pw_vp, w_vp);
    cudaGetSymbolAddress((void**)&pw_op, w_op);
    cudaGetSymbolAddress((void**)&pw_oa, w_oa);
    cudaGetSymbolAddress((void**)&pb_oa, b_oa);
    cudaGetSymbolAddress((void**)&p_q1, g_q1);
    cudaGetSymbolAddress((void**)&p_oa, g_oa);

    const int nW = C * C;
    prep_weights<<<(nW + 255) / 256, 256>>>(vp_w, op_w, vp2_w, op2_w,
                                            so_w, aw_w, so_b, aw_b,
                                            so2_w, aw2_w, so2_b, aw2_b,
                                            pw_vp, pw_op, pw_oa, pb_oa);

    // Stage 1: q1 = query + gamma * MSDeform(LN(query), ref, LN(feat))
    run_stage(query, feat, ref, qn_w, qn_b, fn_w, fn_b, vp_b, op_b, gamma, p_q1,
              p_qn, p_fn, p_samp, p_val, pw_vp, pw_op, pw_oa, pb_oa, p_oa);

    // Stage 2: out = q1 + gamma2 * MSDeform(LN(q1), ref, LN(feat2))
    run_stage(p_q1, feat2, ref, qn2_w, qn2_b, fn2_w, fn2_b, vp2_b, op2_b, gamma2, out,
              p_qn, p_fn, p_samp, p_val, pw_vp + nW, pw_op + nW, pw_oa + NOA * C, pb_oa + NOA,
              p_oa);
}

// round 9
// speedup vs baseline: 4.6169x; 1.1996x over previous
#include <cuda_runtime.h>
#include <cuda_bf16.h>
#include <cstdint>

#define LQ 9216
#define C 768
#define NH 6
#define DH 128
#define NP 4
#define GRID 96
#define NOA 128   // padded offset+aw output width (48 offs + 24 logits + 56 pad)

// ---------------- scratch (no allocations allowed) ----------------
__device__ __nv_bfloat16 s_qn[LQ * C];
__device__ __nv_bfloat16 s_fn[LQ * C];
__device__ __nv_bfloat16 s_samp[LQ * C];
__device__ __nv_bfloat16 s_val[LQ * C];
__device__ __nv_bfloat16 w_vp[2][C * C];
__device__ __nv_bfloat16 w_op[2][C * C];
__device__ __nv_bfloat16 w_oa[2][NOA * C];
__device__ float b_oa[2][NOA];
__device__ float g_q1[LQ * C];
__device__ float g_oa[LQ * NOA];

// ---------------- fused weight prep (1 launch) ----------------
__global__ void prep_weights(const float* __restrict__ vp1, const float* __restrict__ op1,
                             const float* __restrict__ vp2, const float* __restrict__ op2,
                             const float* __restrict__ so1, const float* __restrict__ aw1,
                             const float* __restrict__ so1b, const float* __restrict__ aw1b,
                             const float* __restrict__ so2, const float* __restrict__ aw2,
                             const float* __restrict__ so2b, const float* __restrict__ aw2b,
                             __nv_bfloat16* __restrict__ wvp, __nv_bfloat16* __restrict__ wop,
                             __nv_bfloat16* __restrict__ woa, float* __restrict__ boa) {
    int i = blockIdx.x * 256 + threadIdx.x;
    const int nW = C * C;
    if (i < nW) {
        wvp[i] = __float2bfloat16(vp1[i]);
        wop[i] = __float2bfloat16(op1[i]);
        wvp[nW + i] = __float2bfloat16(vp2[i]);
        wop[nW + i] = __float2bfloat16(op2[i]);
    }
    if (i < NOA * C) {
        float v1 = 0.f, v2 = 0.f;
        if (i < 48 * C) { v1 = so1[i]; v2 = so2[i]; }
        else if (i < 72 * C) { v1 = aw1[i - 48 * C]; v2 = aw2[i - 48 * C]; }
        woa[i] = __float2bfloat16(v1);
        woa[NOA * C + i] = __float2bfloat16(v2);
    }
    if (i < NOA) {
        boa[i]       = (i < 48) ? so1b[i] : (i < 72 ? aw1b[i - 48] : 0.f);
        boa[NOA + i] = (i < 48) ? so2b[i] : (i < 72 ? aw2b[i - 48] : 0.f);
    }
}

// ---------------- dual LayerNorm -> bf16 (2 tensors in one launch) ----------
__global__ __launch_bounds__(192) void ln_dual(const float* __restrict__ xa,
                                               const float* __restrict__ wa,
                                               const float* __restrict__ ba,
                                               __nv_bfloat16* __restrict__ ya,
                                               const float* __restrict__ xb,
                                               const float* __restrict__ wb,
                                               const float* __restrict__ bb,
                                               __nv_bfloat16* __restrict__ yb) {
    int row = blockIdx.x;
    const float *x, *w, *b;
    __nv_bfloat16* y;
    if (row < LQ) { x = xa; w = wa; b = ba; y = ya; }
    else { row -= LQ; x = xb; w = wb; b = bb; y = yb; }

    int t = threadIdx.x;
    int lane = t & 31, wid = t >> 5;
    float4 v = ((const float4*)(x + (size_t)row * C))[t];

    __shared__ float part[6];
    float s = v.x + v.y + v.z + v.w;
    #pragma unroll
    for (int o = 16; o; o >>= 1) s += __shfl_down_sync(0xffffffffu, s, o);
    if (!lane) part[wid] = s;
    __syncthreads();
    float mu = (part[0] + part[1] + part[2] + part[3] + part[4] + part[5]) * (1.f / C);

    float dx = v.x - mu, dy = v.y - mu, dz = v.z - mu, dw = v.w - mu;
    s = dx * dx + dy * dy + dz * dz + dw * dw;
    __syncthreads();
    #pragma unroll
    for (int o = 16; o; o >>= 1) s += __shfl_down_sync(0xffffffffu, s, o);
    if (!lane) part[wid] = s;
    __syncthreads();
    float rs = rsqrtf((part[0] + part[1] + part[2] + part[3] + part[4] + part[5]) * (1.f / C) + 1e-6f);

    float4 wv = ((const float4*)w)[t];
    float4 bv = ((const float4*)b)[t];
    __nv_bfloat162 p0 = __floats2bfloat162_rn(dx * rs * wv.x + bv.x, dy * rs * wv.y + bv.y);
    __nv_bfloat162 p1 = __floats2bfloat162_rn(dz * rs * wv.z + bv.z, dw * rs * wv.w + bv.w);
    __nv_bfloat162* yr = (__nv_bfloat162*)(y + (size_t)row * C);
    yr[t * 2] = p0;
    yr[t * 2 + 1] = p1;
}

// ---------------- bf16 HMMA GEMM, MTx128x32, 3-stage cp.async pipeline -------
#define GBN 128
#define GBK 32
#define LDA 40   // elements; 80B row stride (16B aligned, reduces conflicts)
#define NSTG 3

__device__ __forceinline__ void mma16816(float* c, const uint32_t* a, const uint32_t* b) {
    asm volatile(
        "mma.sync.aligned.m16n8k16.row.col.f32.bf16.bf16.f32 "
        "{%0,%1,%2,%3}, {%4,%5,%6,%7}, {%8,%9}, {%0,%1,%2,%3};\n"
        : "+f"(c[0]), "+f"(c[1]), "+f"(c[2]), "+f"(c[3])
        : "r"(a[0]), "r"(a[1]), "r"(a[2]), "r"(a[3]), "r"(b[0]), "r"(b[1]));
}

__device__ __forceinline__ void cp16(uint32_t s, const void* g) {
    asm volatile("cp.async.cg.shared.global [%0], [%1], 16;\n" :: "r"(s), "l"(g));
}

// MODE 0: out = acc + bias ; MODE 1: out = resid + gamma*(acc+bias)
// OUT_BF16: store bf16 instead of float. MT: rows per block tile (128 or 64).
template <int MODE, bool OUT_BF16, int MT>
__global__ __launch_bounds__(256, 2) void gemm_bf16(const __nv_bfloat16* __restrict__ A,
                                                    const __nv_bfloat16* __restrict__ B,
                                                    const float* __restrict__ bias,
                                                    const float* __restrict__ resid,
                                                    const float* __restrict__ gamma,
                                                    void* __restrict__ Cout,
                                                    int M, int N, int K) {
    extern __shared__ __nv_bfloat16 smem[];
    const uint32_t STGB = (MT + GBN) * LDA * 2;   // bytes per stage
    const uint32_t BOFF = MT * LDA * 2;           // B offset within a stage

    int tid = threadIdx.x;
    int warp = tid >> 5, lane = tid & 31;
    int bm = blockIdx.y * MT, bn = blockIdx.x * GBN;
    const int MA = MT / 64;                        // 16-row MMA tiles per warp
    int wm = (warp >> 1) * (MT / 4);               // 4 warps along m
    int wn = (warp & 1) * 64;                      // 2 warps along n

    uint32_t sBase = (uint32_t)__cvta_generic_to_shared(smem);

    // ldmatrix fragment base addresses (stage 0)
    uint32_t a_addr[MA][2], b_addr[4][2];
    #pragma unroll
    for (int ma = 0; ma < MA; ma++)
        #pragma unroll
        for (int ks = 0; ks < 2; ks++)
            a_addr[ma][ks] = sBase +
                ((wm + ma * 16 + (lane & 15)) * LDA + ks * 16 + (lane >> 4) * 8) * 2;
    #pragma unroll
    for (int pr = 0; pr < 4; pr++)
        #pragma unroll
        for (int ks = 0; ks < 2; ks++)
            b_addr[pr][ks] = sBase + BOFF +
                ((wn + pr * 16 + (lane & 15)) * LDA + ks * 16 + (lane >> 4) * 8) * 2;

    const __nv_bfloat16* Abase = A + (size_t)bm * K;
    const __nv_bfloat16* Bbase = B + (size_t)bn * K;

    auto load_stage = [&](int stage, int k0) {
        uint32_t so = sBase + stage * STGB;
        #pragma unroll
        for (int i = 0; i < MT * 4; i += 256) {
            int idx = i + tid;
            int r = idx >> 2, c = (idx & 3) * 8;
            cp16(so + r * (LDA * 2) + c * 2, Abase + (size_t)r * K + k0 + c);
        }
        #pragma unroll
        for (int i = 0; i < 512; i += 256) {
            int idx = i + tid;
            int r = idx >> 2, c = (idx & 3) * 8;
            cp16(so + BOFF + r * (LDA * 2) + c * 2, Bbase + (size_t)r * K + k0 + c);
        }
        asm volatile("cp.async.commit_group;\n");
    };

    float acc[MA][8][4] = {};

    const int NK = K / GBK;   // >= 2 always (K=768 -> 24)
    load_stage(0, 0);
    load_stage(1, GBK);

    for (int it = 0; it < NK; it++) {
        if (it + 1 < NK)
            asm volatile("cp.async.wait_group 1;\n");
        else
            asm volatile("cp.async.wait_group 0;\n");
        __syncthreads();   // all warps done reading stage it-1's buffer

        if (it + 2 < NK) load_stage((it + 2) % NSTG, (it + 2) * GBK);

        uint32_t soff = (it % NSTG) * STGB;
        #pragma unroll
        for (int ks = 0; ks < 2; ks++) {
            uint32_t af[MA][4], bf[8][2];
            #pragma unroll
            for (int ma = 0; ma < MA; ma++)
                asm volatile("ldmatrix.sync.aligned.m8n8.x4.shared.b16 {%0,%1,%2,%3}, [%4];"
                             : "=r"(af[ma][0]), "=r"(af[ma][1]), "=r"(af[ma][2]), "=r"(af[ma][3])
                             : "r"(a_addr[ma][ks] + soff));
            #pragma unroll
            for (int pr = 0; pr < 4; pr++) {
                uint32_t r0, r1, r2, r3;
                asm volatile("ldmatrix.sync.aligned.m8n8.x4.shared.b16 {%0,%1,%2,%3}, [%4];"
                             : "=r"(r0), "=r"(r1), "=r"(r2), "=r"(r3)
                             : "r"(b_addr[pr][ks] + soff));
                bf[pr * 2 + 0][0] = r0; bf[pr * 2 + 0][1] = r2;
                bf[pr * 2 + 1][0] = r1; bf[pr * 2 + 1][1] = r3;
            }
            #pragma unroll
            for (int ma = 0; ma < MA; ma++)
                #pragma unroll
                for (int na = 0; na < 8; na++)
                    mma16816(acc[ma][na], af[ma], bf[na]);
        }
    }

    int tr = lane >> 2, tc = (lane & 3) * 2;
    #pragma unroll
    for (int ma = 0; ma < MA; ma++) {
        #pragma unroll
        for (int half = 0; half < 2; half++) {
            int m = bm + wm + ma * 16 + half * 8 + tr;
            #pragma unroll
            for (int na = 0; na < 8; na++) {
                int n = bn + wn + na * 8 + tc;
                float v0 = acc[ma][na][half * 2 + 0] + bias[n];
                float v1 = acc[ma][na][half * 2 + 1] + bias[n + 1];
                if (MODE == 1) {
                    v0 = resid[(size_t)m * N + n] + gamma[n] * v0;
                    v1 = resid[(size_t)m * N + n + 1] + gamma[n + 1] * v1;
                }
                if (OUT_BF16)
                    *(__nv_bfloat162*)((__nv_bfloat16*)Cout + (size_t)m * N + n) =
                        __floats2bfloat162_rn(v0, v1);
                else
                    *(float2*)((float*)Cout + (size_t)m * N + n) = make_float2(v0, v1);
            }
        }
    }
}

// ---------------- bilinear deformable sampling (bf16x2, 2 ch/thread) --------
__device__ __forceinline__ float2 fetchv2(const __nv_bfloat162* __restrict__ val,
                                          int y, int x, int t) {
    if ((unsigned)y < (unsigned)GRID && (unsigned)x < (unsigned)GRID) {
        __nv_bfloat162 v = __ldg(&val[(size_t)(y * GRID + x) * (C / 2) + t]);
        return make_float2(__bfloat162float(v.x), __bfloat162float(v.y));
    }
    return make_float2(0.f, 0.f);
}

__global__ __launch_bounds__(384) void sampler_kernel(const __nv_bfloat162* __restrict__ val,
                                                      const float* __restrict__ ref,
                                                      const float* __restrict__ oa,
                                                      __nv_bfloat162* __restrict__ out) {
    int q = blockIdx.x;
    int tid = threadIdx.x;
    __shared__ float s[72];
    if (tid < 72) s[tid] = oa[(size_t)q * NOA + tid];
    __syncthreads();

    int h = tid >> 6;   // 64 bf16x2-pairs per head
    float refx = ref[q * 2];
    float refy = ref[q * 2 + 1];

    float lg[4];
    #pragma unroll
    for (int p = 0; p < NP; p++) lg[p] = s[48 + h * 4 + p];
    float mx = fmaxf(fmaxf(lg[0], lg[1]), fmaxf(lg[2], lg[3]));
    float e[4];
    float se = 0.f;
    #pragma unroll
    for (int p = 0; p < NP; p++) { e[p] = __expf(lg[p] - mx); se += e[p]; }
    float inv = 1.f / se;

    float ax = 0.f, ay = 0.f;
    #pragma unroll
    for (int p = 0; p < NP; p++) {
        float px = refx * (float)GRID + s[(h * 4 + p) * 2]     - 0.5f;
        float py = refy * (float)GRID + s[(h * 4 + p) * 2 + 1] - 0.5f;
        float fx0 = floorf(px), fy0 = floorf(py);
        int x0 = (int)fx0, y0 = (int)fy0;
        float fx = px - fx0, fy = py - fy0;
        float w00 = (1.f - fy) * (1.f - fx);
        float w01 = (1.f - fy) * fx;
        float w10 = fy * (1.f - fx);
        float w11 = fy * fx;
        float2 v00 = fetchv2(val, y0,     x0,     tid);
        float2 v01 = fetchv2(val, y0,     x0 + 1, tid);
        float2 v10 = fetchv2(val, y0 + 1, x0,     tid);
        float2 v11 = fetchv2(val, y0 + 1, x0 + 1, tid);
        float wp = e[p] * inv;
        ax = fmaf(wp, w00 * v00.x + w01 * v01.x + w10 * v10.x + w11 * v11.x, ax);
        ay = fmaf(wp, w00 * v00.y + w01 * v01.y + w10 * v10.y + w11 * v11.y, ay);
    }
    out[(size_t)q * (C / 2) + tid] = __floats2bfloat162_rn(ax, ay);
}

// ---------------- host side ----------------
#define SMEM_BIG (NSTG * (128 + GBN) * LDA * 2)   // 61440 B
#define SMEM_OA  (NSTG * (64 + GBN) * LDA * 2)    // 46080 B

static void run_stage(const float* q_in, const float* feat, const float* ref,
                      const float* qn_w, const float* qn_b,
                      const float* fn_w, const float* fn_b,
                      const float* vp_b, const float* op_b,
                      const float* gamma, float* q_out,
                      __nv_bfloat16* p_qn, __nv_bfloat16* p_fn, __nv_bfloat16* p_samp,
                      __nv_bfloat16* p_val,
                      const __nv_bfloat16* pw_vp, const __nv_bfloat16* pw_op,
                      const __nv_bfloat16* pw_oa, const float* pb_oa,
                      float* p_oa) {
    ln_dual<<<2 * LQ, 192>>>(q_in, qn_w, qn_b, p_qn, feat, fn_w, fn_b, p_fn);
    gemm_bf16<0, true, 128><<<dim3(C / GBN, LQ / 128), 256, SMEM_BIG>>>(
        p_fn, pw_vp, vp_b, nullptr, nullptr, p_val, LQ, C, C);
    gemm_bf16<0, false, 64><<<dim3(1, LQ / 64), 256, SMEM_OA>>>(
        p_qn, pw_oa, pb_oa, nullptr, nullptr, p_oa, LQ, NOA, C);
    sampler_kernel<<<LQ, 384>>>((const __nv_bfloat162*)p_val, ref, p_oa,
                                (__nv_bfloat162*)p_samp);
    gemm_bf16<1, false, 128><<<dim3(C / GBN, LQ / 128), 256, SMEM_BIG>>>(
        p_samp, pw_op, op_b, q_in, gamma, q_out, LQ, C, C);
}

extern "C" void kernel_launch(void* const* d_in, const int* in_sizes, int n_in,
                              void* d_out, int out_size) {
    const float* query = (const float*)d_in[0];
    const float* ref   = (const float*)d_in[1];
    const float* feat  = (const float*)d_in[2];
    const float* feat2 = (const float*)d_in[3];
    const float* qn_w = (const float*)d_in[6];
    const float* qn_b = (const float*)d_in[7];
    const float* fn_w = (const float*)d_in[8];
    const float* fn_b = (const float*)d_in[9];
    const float* so_w = (const float*)d_in[10];
    const float* so_b = (const float*)d_in[11];
    const float* aw_w = (const float*)d_in[12];
    const float* aw_b = (const float*)d_in[13];
    const float* vp_w = (const float*)d_in[14];
    const float* vp_b = (const float*)d_in[15];
    const float* op_w = (const float*)d_in[16];
    const float* op_b = (const float*)d_in[17];
    const float* gamma = (const float*)d_in[18];
    const float* qn2_w = (const float*)d_in[19];
    const float* qn2_b = (const float*)d_in[20];
    const float* fn2_w = (const float*)d_in[21];
    const float* fn2_b = (const float*)d_in[22];
    const float* so2_w = (const float*)d_in[23];
    const float* so2_b = (const float*)d_in[24];
    const float* aw2_w = (const float*)d_in[25];
    const float* aw2_b = (const float*)d_in[26];
    const float* vp2_w = (const float*)d_in[27];
    const float* vp2_b = (const float*)d_in[28];
    const float* op2_w = (const float*)d_in[29];
    const float* op2_b = (const float*)d_in[30];
    const float* gamma2 = (const float*)d_in[31];
    float* out = (float*)d_out;

    __nv_bfloat16 *p_qn, *p_fn, *p_samp, *p_val, *pw_vp, *pw_op, *pw_oa;
    float *p_q1, *p_oa, *pb_oa;
    cudaGetSymbolAddress((void**)&p_qn, s_qn);
    cudaGetSymbolAddress((void**)&p_fn, s_fn);
    cudaGetSymbolAddress((void**)&p_samp, s_samp);
    cudaGetSymbolAddress((void**)&p_val, s_val);
    cudaGetSymbolAddress((void**)&pw_vp, w_vp);
    cudaGetSymbolAddress((void**)&pw_op, w_op);
    cudaGetSymbolAddress((void**)&pw_oa, w_oa);
    cudaGetSymbolAddress((void**)&pb_oa, b_oa);
    cudaGetSymbolAddress((void**)&p_q1, g_q1);
    cudaGetSymbolAddress((void**)&p_oa, g_oa);

    // opt-in dynamic smem > 48KB (host-side attribute set; not captured)
    static bool attr_done = false;
    if (!attr_done) {
        cudaFuncSetAttribute(gemm_bf16<0, true, 128>,
                             cudaFuncAttributeMaxDynamicSharedMemorySize, SMEM_BIG);
        cudaFuncSetAttribute(gemm_bf16<1, false, 128>,
                             cudaFuncAttributeMaxDynamicSharedMemorySize, SMEM_BIG);
        cudaFuncSetAttribute(gemm_bf16<0, false, 64>,
                             cudaFuncAttributeMaxDynamicSharedMemorySize, SMEM_OA);
        attr_done = true;
    }

    const int nW = C * C;
    prep_weights<<<(nW + 255) / 256, 256>>>(vp_w, op_w, vp2_w, op2_w,
                                            so_w, aw_w, so_b, aw_b,
                                            so2_w, aw2_w, so2_b, aw2_b,
                                            pw_vp, pw_op, pw_oa, pb_oa);

    // Stage 1: q1 = query + gamma * MSDeform(LN(query), ref, LN(feat))
    run_stage(query, feat, ref, qn_w, qn_b, fn_w, fn_b, vp_b, op_b, gamma, p_q1,
              p_qn, p_fn, p_samp, p_val, pw_vp, pw_op, pw_oa, pb_oa, p_oa);

    // Stage 2: out = q1 + gamma2 * MSDeform(LN(q1), ref, LN(feat2))
    run_stage(p_q1, feat2, ref, qn2_w, qn2_b, fn2_w, fn2_b, vp2_b, op2_b, gamma2, out,
              p_qn, p_fn, p_samp, p_val, pw_vp + nW, pw_op + nW, pw_oa + NOA * C, pb_oa + NOA,
              p_oa);
}

// round 10
// speedup vs baseline: 4.7353x; 1.0257x over previous
#include <cuda_runtime.h>
#include <cuda_bf16.h>
#include <cstdint>

#define LQ 9216
#define C 768
#define NH 6
#define DH 128
#define NP 4
#define GRID 96
#define NOA 128   // padded offset+aw output width (48 offs + 24 logits + 56 pad)

// ---------------- scratch (no allocations allowed) ----------------
__device__ __nv_bfloat16 s_qn[LQ * C];
__device__ __nv_bfloat16 s_fn[LQ * C];
__device__ __nv_bfloat16 s_samp[LQ * C];
__device__ __nv_bfloat16 s_val[LQ * C];
__device__ __nv_bfloat16 w_vp[2][C * C];
__device__ __nv_bfloat16 w_op[2][C * C];
__device__ __nv_bfloat16 w_oa[2][NOA * C];
__device__ float b_oa[2][NOA];
__device__ float g_q1[LQ * C];
__device__ float g_oa[LQ * NOA];

// ---------------- fused weight prep (1 launch) ----------------
__global__ void prep_weights(const float* __restrict__ vp1, const float* __restrict__ op1,
                             const float* __restrict__ vp2, const float* __restrict__ op2,
                             const float* __restrict__ so1, const float* __restrict__ aw1,
                             const float* __restrict__ so1b, const float* __restrict__ aw1b,
                             const float* __restrict__ so2, const float* __restrict__ aw2,
                             const float* __restrict__ so2b, const float* __restrict__ aw2b,
                             __nv_bfloat16* __restrict__ wvp, __nv_bfloat16* __restrict__ wop,
                             __nv_bfloat16* __restrict__ woa, float* __restrict__ boa) {
    int i = blockIdx.x * 256 + threadIdx.x;
    const int nW = C * C;
    if (i < nW) {
        wvp[i] = __float2bfloat16(vp1[i]);
        wop[i] = __float2bfloat16(op1[i]);
        wvp[nW + i] = __float2bfloat16(vp2[i]);
        wop[nW + i] = __float2bfloat16(op2[i]);
    }
    if (i < NOA * C) {
        float v1 = 0.f, v2 = 0.f;
        if (i < 48 * C) { v1 = so1[i]; v2 = so2[i]; }
        else if (i < 72 * C) { v1 = aw1[i - 48 * C]; v2 = aw2[i - 48 * C]; }
        woa[i] = __float2bfloat16(v1);
        woa[NOA * C + i] = __float2bfloat16(v2);
    }
    if (i < NOA) {
        boa[i]       = (i < 48) ? so1b[i] : (i < 72 ? aw1b[i - 48] : 0.f);
        boa[NOA + i] = (i < 48) ? so2b[i] : (i < 72 ? aw2b[i - 48] : 0.f);
    }
}

// ---------------- dual LayerNorm -> bf16 (2 tensors in one launch) ----------
__global__ __launch_bounds__(192) void ln_dual(const float* __restrict__ xa,
                                               const float* __restrict__ wa,
                                               const float* __restrict__ ba,
                                               __nv_bfloat16* __restrict__ ya,
                                               const float* __restrict__ xb,
                                               const float* __restrict__ wb,
                                               const float* __restrict__ bb,
                                               __nv_bfloat16* __restrict__ yb) {
    int row = blockIdx.x;
    const float *x, *w, *b;
    __nv_bfloat16* y;
    if (row < LQ) { x = xa; w = wa; b = ba; y = ya; }
    else { row -= LQ; x = xb; w = wb; b = bb; y = yb; }

    int t = threadIdx.x;
    int lane = t & 31, wid = t >> 5;
    float4 v = ((const float4*)(x + (size_t)row * C))[t];

    __shared__ float part[6];
    float s = v.x + v.y + v.z + v.w;
    #pragma unroll
    for (int o = 16; o; o >>= 1) s += __shfl_down_sync(0xffffffffu, s, o);
    if (!lane) part[wid] = s;
    __syncthreads();
    float mu = (part[0] + part[1] + part[2] + part[3] + part[4] + part[5]) * (1.f / C);

    float dx = v.x - mu, dy = v.y - mu, dz = v.z - mu, dw = v.w - mu;
    s = dx * dx + dy * dy + dz * dz + dw * dw;
    __syncthreads();
    #pragma unroll
    for (int o = 16; o; o >>= 1) s += __shfl_down_sync(0xffffffffu, s, o);
    if (!lane) part[wid] = s;
    __syncthreads();
    float rs = rsqrtf((part[0] + part[1] + part[2] + part[3] + part[4] + part[5]) * (1.f / C) + 1e-6f);

    float4 wv = ((const float4*)w)[t];
    float4 bv = ((const float4*)b)[t];
    __nv_bfloat162 p0 = __floats2bfloat162_rn(dx * rs * wv.x + bv.x, dy * rs * wv.y + bv.y);
    __nv_bfloat162 p1 = __floats2bfloat162_rn(dz * rs * wv.z + bv.z, dw * rs * wv.w + bv.w);
    __nv_bfloat162* yr = (__nv_bfloat162*)(y + (size_t)row * C);
    yr[t * 2] = p0;
    yr[t * 2 + 1] = p1;
}

// ---------------- bf16 HMMA GEMM, 64x128x32, 3-stage cp.async pipeline -------
#define MT 64
#define GBN 128
#define GBK 32
#define LDA 40   // elements; 80B row stride (16B aligned, reduces conflicts)
#define NSTG 3

__device__ __forceinline__ void mma16816(float* c, const uint32_t* a, const uint32_t* b) {
    asm volatile(
        "mma.sync.aligned.m16n8k16.row.col.f32.bf16.bf16.f32 "
        "{%0,%1,%2,%3}, {%4,%5,%6,%7}, {%8,%9}, {%0,%1,%2,%3};\n"
        : "+f"(c[0]), "+f"(c[1]), "+f"(c[2]), "+f"(c[3])
        : "r"(a[0]), "r"(a[1]), "r"(a[2]), "r"(a[3]), "r"(b[0]), "r"(b[1]));
}

__device__ __forceinline__ void cp16(uint32_t s, const void* g) {
    asm volatile("cp.async.cg.shared.global [%0], [%1], 16;\n" :: "r"(s), "l"(g));
}

// MODE 0: out = acc + bias ; MODE 1: out = resid + gamma*(acc+bias)
// OUT_BF16: store bf16 instead of float.
template <int MODE, bool OUT_BF16>
__global__ __launch_bounds__(256, 2) void gemm_bf16(const __nv_bfloat16* __restrict__ A,
                                                    const __nv_bfloat16* __restrict__ B,
                                                    const float* __restrict__ bias,
                                                    const float* __restrict__ resid,
                                                    const float* __restrict__ gamma,
                                                    void* __restrict__ Cout,
                                                    int M, int N, int K) {
    extern __shared__ __nv_bfloat16 smem[];
    const uint32_t STGB = (MT + GBN) * LDA * 2;   // bytes per stage
    const uint32_t BOFF = MT * LDA * 2;           // B offset within a stage

    int tid = threadIdx.x;
    int warp = tid >> 5, lane = tid & 31;
    int bm = blockIdx.y * MT, bn = blockIdx.x * GBN;
    int wm = (warp >> 1) * 16;                     // 4 warps along m (16 rows each)
    int wn = (warp & 1) * 64;                      // 2 warps along n

    uint32_t sBase = (uint32_t)__cvta_generic_to_shared(smem);

    // ldmatrix fragment base addresses (stage 0)
    uint32_t a_addr[2], b_addr[4][2];
    #pragma unroll
    for (int ks = 0; ks < 2; ks++)
        a_addr[ks] = sBase +
            ((wm + (lane & 15)) * LDA + ks * 16 + (lane >> 4) * 8) * 2;
    #pragma unroll
    for (int pr = 0; pr < 4; pr++)
        #pragma unroll
        for (int ks = 0; ks < 2; ks++)
            b_addr[pr][ks] = sBase + BOFF +
                ((wn + pr * 16 + (lane & 15)) * LDA + ks * 16 + (lane >> 4) * 8) * 2;

    const __nv_bfloat16* Abase = A + (size_t)bm * K;
    const __nv_bfloat16* Bbase = B + (size_t)bn * K;

    auto load_stage = [&](int stage, int k0) {
        uint32_t so = sBase + stage * STGB;
        {   // A: 64 rows * 4 chunks = 256 slots, 1 per thread
            int r = tid >> 2, c = (tid & 3) * 8;
            cp16(so + r * (LDA * 2) + c * 2, Abase + (size_t)r * K + k0 + c);
        }
        #pragma unroll
        for (int i = 0; i < 512; i += 256) {   // B: 128 rows * 4 chunks
            int idx = i + tid;
            int r = idx >> 2, c = (idx & 3) * 8;
            cp16(so + BOFF + r * (LDA * 2) + c * 2, Bbase + (size_t)r * K + k0 + c);
        }
        asm volatile("cp.async.commit_group;\n");
    };

    float acc[8][4] = {};

    const int NK = K / GBK;   // 24
    load_stage(0, 0);
    load_stage(1, GBK);

    for (int it = 0; it < NK; it++) {
        if (it + 1 < NK)
            asm volatile("cp.async.wait_group 1;\n");
        else
            asm volatile("cp.async.wait_group 0;\n");
        __syncthreads();

        if (it + 2 < NK) load_stage((it + 2) % NSTG, (it + 2) * GBK);

        uint32_t soff = (it % NSTG) * STGB;
        #pragma unroll
        for (int ks = 0; ks < 2; ks++) {
            uint32_t af[4], bf[8][2];
            asm volatile("ldmatrix.sync.aligned.m8n8.x4.shared.b16 {%0,%1,%2,%3}, [%4];"
                         : "=r"(af[0]), "=r"(af[1]), "=r"(af[2]), "=r"(af[3])
                         : "r"(a_addr[ks] + soff));
            #pragma unroll
            for (int pr = 0; pr < 4; pr++) {
                uint32_t r0, r1, r2, r3;
                asm volatile("ldmatrix.sync.aligned.m8n8.x4.shared.b16 {%0,%1,%2,%3}, [%4];"
                             : "=r"(r0), "=r"(r1), "=r"(r2), "=r"(r3)
                             : "r"(b_addr[pr][ks] + soff));
                bf[pr * 2 + 0][0] = r0; bf[pr * 2 + 0][1] = r2;
                bf[pr * 2 + 1][0] = r1; bf[pr * 2 + 1][1] = r3;
            }
            #pragma unroll
            for (int na = 0; na < 8; na++)
                mma16816(acc[na], af, bf[na]);
        }
    }

    int tr = lane >> 2, tc = (lane & 3) * 2;
    #pragma unroll
    for (int half = 0; half < 2; half++) {
        int m = bm + wm + half * 8 + tr;
        #pragma unroll
        for (int na = 0; na < 8; na++) {
            int n = bn + wn + na * 8 + tc;
            float v0 = acc[na][half * 2 + 0] + bias[n];
            float v1 = acc[na][half * 2 + 1] + bias[n + 1];
            if (MODE == 1) {
                v0 = resid[(size_t)m * N + n] + gamma[n] * v0;
                v1 = resid[(size_t)m * N + n + 1] + gamma[n + 1] * v1;
            }
            if (OUT_BF16)
                *(__nv_bfloat162*)((__nv_bfloat16*)Cout + (size_t)m * N + n) =
                    __floats2bfloat162_rn(v0, v1);
            else
                *(float2*)((float*)Cout + (size_t)m * N + n) = make_float2(v0, v1);
        }
    }
}

// ---------------- bilinear sampling: 4 ch/thread (uint2), 2 queries/block ----
__device__ __forceinline__ void fetch4(const uint2* __restrict__ val, int y, int x, int t,
                                       float* o) {
    if ((unsigned)y < (unsigned)GRID && (unsigned)x < (unsigned)GRID) {
        uint2 raw = __ldg(&val[(size_t)(y * GRID + x) * (C / 4) + t]);
        __nv_bfloat162 a = *(__nv_bfloat162*)&raw.x;
        __nv_bfloat162 b = *(__nv_bfloat162*)&raw.y;
        o[0] = __bfloat162float(a.x); o[1] = __bfloat162float(a.y);
        o[2] = __bfloat162float(b.x); o[3] = __bfloat162float(b.y);
    } else {
        o[0] = o[1] = o[2] = o[3] = 0.f;
    }
}

__global__ __launch_bounds__(384) void sampler_kernel(const uint2* __restrict__ val,
                                                      const float* __restrict__ ref,
                                                      const float* __restrict__ oa,
                                                      uint2* __restrict__ out) {
    int q0 = blockIdx.x * 2;
    int tid = threadIdx.x;
    __shared__ float s[2][72];
    if (tid < 144) s[tid / 72][tid % 72] = oa[(size_t)(q0 + tid / 72) * NOA + tid % 72];
    __syncthreads();

    int lq = tid / 192;      // 0/1: which query in the pair
    int t = tid % 192;       // channel quad 0..191
    int h = t >> 5;          // head (32 quads = 128 channels)
    int q = q0 + lq;
    const float* sq = s[lq];
    float refx = ref[q * 2];
    float refy = ref[q * 2 + 1];

    float lg[4];
    #pragma unroll
    for (int p = 0; p < NP; p++) lg[p] = sq[48 + h * 4 + p];
    float mx = fmaxf(fmaxf(lg[0], lg[1]), fmaxf(lg[2], lg[3]));
    float e[4];
    float se = 0.f;
    #pragma unroll
    for (int p = 0; p < NP; p++) { e[p] = __expf(lg[p] - mx); se += e[p]; }
    float inv = 1.f / se;

    float acc[4] = {};
    #pragma unroll
    for (int p = 0; p < NP; p++) {
        float px = refx * (float)GRID + sq[(h * 4 + p) * 2]     - 0.5f;
        float py = refy * (float)GRID + sq[(h * 4 + p) * 2 + 1] - 0.5f;
        float fx0 = floorf(px), fy0 = floorf(py);
        int x0 = (int)fx0, y0 = (int)fy0;
        float fx = px - fx0, fy = py - fy0;
        float w00 = (1.f - fy) * (1.f - fx);
        float w01 = (1.f - fy) * fx;
        float w10 = fy * (1.f - fx);
        float w11 = fy * fx;
        float v00[4], v01[4], v10[4], v11[4];
        fetch4(val, y0,     x0,     t, v00);
        fetch4(val, y0,     x0 + 1, t, v01);
        fetch4(val, y0 + 1, x0,     t, v10);
        fetch4(val, y0 + 1, x0 + 1, t, v11);
        float wp = e[p] * inv;
        #pragma unroll
        for (int c = 0; c < 4; c++)
            acc[c] = fmaf(wp, w00 * v00[c] + w01 * v01[c] + w10 * v10[c] + w11 * v11[c],
                          acc[c]);
    }
    uint2 packed;
    __nv_bfloat162 pa = __floats2bfloat162_rn(acc[0], acc[1]);
    __nv_bfloat162 pb = __floats2bfloat162_rn(acc[2], acc[3]);
    packed.x = *(uint32_t*)&pa;
    packed.y = *(uint32_t*)&pb;
    out[(size_t)q * (C / 4) + t] = packed;
}

// ---------------- host side ----------------
#define SMEM_GEMM (NSTG * (MT + GBN) * LDA * 2)   // 46080 B

static void run_stage(const float* q_in, const float* feat, const float* ref,
                      const float* qn_w, const float* qn_b,
                      const float* fn_w, const float* fn_b,
                      const float* vp_b, const float* op_b,
                      const float* gamma, float* q_out,
                      __nv_bfloat16* p_qn, __nv_bfloat16* p_fn, __nv_bfloat16* p_samp,
                      __nv_bfloat16* p_val,
                      const __nv_bfloat16* pw_vp, const __nv_bfloat16* pw_op,
                      const __nv_bfloat16* pw_oa, const float* pb_oa,
                      float* p_oa) {
    ln_dual<<<2 * LQ, 192>>>(q_in, qn_w, qn_b, p_qn, feat, fn_w, fn_b, p_fn);
    gemm_bf16<0, true><<<dim3(C / GBN, LQ / MT), 256, SMEM_GEMM>>>(
        p_fn, pw_vp, vp_b, nullptr, nullptr, p_val, LQ, C, C);
    gemm_bf16<0, false><<<dim3(1, LQ / MT), 256, SMEM_GEMM>>>(
        p_qn, pw_oa, pb_oa, nullptr, nullptr, p_oa, LQ, NOA, C);
    sampler_kernel<<<LQ / 2, 384>>>((const uint2*)p_val, ref, p_oa, (uint2*)p_samp);
    gemm_bf16<1, false><<<dim3(C / GBN, LQ / MT), 256, SMEM_GEMM>>>(
        p_samp, pw_op, op_b, q_in, gamma, q_out, LQ, C, C);
}

extern "C" void kernel_launch(void* const* d_in, const int* in_sizes, int n_in,
                              void* d_out, int out_size) {
    const float* query = (const float*)d_in[0];
    const float* ref   = (const float*)d_in[1];
    const float* feat  = (const float*)d_in[2];
    const float* feat2 = (const float*)d_in[3];
    const float* qn_w = (const float*)d_in[6];
    const float* qn_b = (const float*)d_in[7];
    const float* fn_w = (const float*)d_in[8];
    const float* fn_b = (const float*)d_in[9];
    const float* so_w = (const float*)d_in[10];
    const float* so_b = (const float*)d_in[11];
    const float* aw_w = (const float*)d_in[12];
    const float* aw_b = (const float*)d_in[13];
    const float* vp_w = (const float*)d_in[14];
    const float* vp_b = (const float*)d_in[15];
    const float* op_w = (const float*)d_in[16];
    const float* op_b = (const float*)d_in[17];
    const float* gamma = (const float*)d_in[18];
    const float* qn2_w = (const float*)d_in[19];
    const float* qn2_b = (const float*)d_in[20];
    const float* fn2_w = (const float*)d_in[21];
    const float* fn2_b = (const float*)d_in[22];
    const float* so2_w = (const float*)d_in[23];
    const float* so2_b = (const float*)d_in[24];
    const float* aw2_w = (const float*)d_in[25];
    const float* aw2_b = (const float*)d_in[26];
    const float* vp2_w = (const float*)d_in[27];
    const float* vp2_b = (const float*)d_in[28];
    const float* op2_w = (const float*)d_in[29];
    const float* op2_b = (const float*)d_in[30];
    const float* gamma2 = (const float*)d_in[31];
    float* out = (float*)d_out;

    __nv_bfloat16 *p_qn, *p_fn, *p_samp, *p_val, *pw_vp, *pw_op, *pw_oa;
    float *p_q1, *p_oa, *pb_oa;
    cudaGetSymbolAddress((void**)&p_qn, s_qn);
    cudaGetSymbolAddress((void**)&p_fn, s_fn);
    cudaGetSymbolAddress((void**)&p_samp, s_samp);
    cudaGetSymbolAddress((void**)&p_val, s_val);
    cudaGetSymbolAddress((void**)&pw_vp, w_vp);
    cudaGetSymbolAddress((void**)&pw_op, w_op);
    cudaGetSymbolAddress((void**)&pw_oa, w_oa);
    cudaGetSymbolAddress((void**)&pb_oa, b_oa);
    cudaGetSymbolAddress((void**)&p_q1, g_q1);
    cudaGetSymbolAddress((void**)&p_oa, g_oa);

    static bool attr_done = false;
    if (!attr_done) {
        cudaFuncSetAttribute(gemm_bf16<0, true>,
                             cudaFuncAttributeMaxDynamicSharedMemorySize, SMEM_GEMM);
        cudaFuncSetAttribute(gemm_bf16<1, false>,
                             cudaFuncAttributeMaxDynamicSharedMemorySize, SMEM_GEMM);
        cudaFuncSetAttribute(gemm_bf16<0, false>,
                             cudaFuncAttributeMaxDynamicSharedMemorySize, SMEM_GEMM);
        attr_done = true;
    }

    const int nW = C * C;
    prep_weights<<<(nW + 255) / 256, 256>>>(vp_w, op_w, vp2_w, op2_w,
                                            so_w, aw_w, so_b, aw_b,
                                            so2_w, aw2_w, so2_b, aw2_b,
                                            pw_vp, pw_op, pw_oa, pb_oa);

    // Stage 1: q1 = query + gamma * MSDeform(LN(query), ref, LN(feat))
    run_stage(query, feat, ref, qn_w, qn_b, fn_w, fn_b, vp_b, op_b, gamma, p_q1,
              p_qn, p_fn, p_samp, p_val, pw_vp, pw_op, pw_oa, pb_oa, p_oa);

    // Stage 2: out = q1 + gamma2 * MSDeform(LN(q1), ref, LN(feat2))
    run_stage(p_q1, feat2, ref, qn2_w, qn2_b, fn2_w, fn2_b, vp2_b, op2_b, gamma2, out,
              p_qn, p_fn, p_samp, p_val, pw_vp + nW, pw_op + nW, pw_oa + NOA * C, pb_oa + NOA,
              p_oa);
}

// round 11
// speedup vs baseline: 5.0048x; 1.0569x over previous
#include <cuda_runtime.h>
#include <cuda_bf16.h>
#include <cstdint>

#define LQ 9216
#define C 768
#define NH 6
#define DH 128
#define NP 4
#define GRID 96
#define NOA 128   // padded offset+aw output width (48 offs + 24 logits + 56 pad)

// ---------------- scratch (no allocations allowed) ----------------
__device__ __nv_bfloat16 s_qn[LQ * C];
__device__ __nv_bfloat16 s_fn[LQ * C];
__device__ __nv_bfloat16 s_fn2[LQ * C];
__device__ __nv_bfloat16 s_samp[LQ * C];
__device__ __nv_bfloat16 s_val[LQ * C];
__device__ __nv_bfloat16 s_val2[LQ * C];
__device__ __nv_bfloat16 w_vp[2][C * C];
__device__ __nv_bfloat16 w_op[2][C * C];
__device__ __nv_bfloat16 w_oa[2][NOA * C];
__device__ float b_oa[2][NOA];
__device__ float g_q1[LQ * C];
__device__ float g_oa[LQ * NOA];

// ---------------- fused weight prep (1 launch) ----------------
__global__ void prep_weights(const float* __restrict__ vp1, const float* __restrict__ op1,
                             const float* __restrict__ vp2, const float* __restrict__ op2,
                             const float* __restrict__ so1, const float* __restrict__ aw1,
                             const float* __restrict__ so1b, const float* __restrict__ aw1b,
                             const float* __restrict__ so2, const float* __restrict__ aw2,
                             const float* __restrict__ so2b, const float* __restrict__ aw2b,
                             __nv_bfloat16* __restrict__ wvp, __nv_bfloat16* __restrict__ wop,
                             __nv_bfloat16* __restrict__ woa, float* __restrict__ boa) {
    int i = blockIdx.x * 256 + threadIdx.x;
    const int nW = C * C;
    if (i < nW) {
        wvp[i] = __float2bfloat16(vp1[i]);
        wop[i] = __float2bfloat16(op1[i]);
        wvp[nW + i] = __float2bfloat16(vp2[i]);
        wop[nW + i] = __float2bfloat16(op2[i]);
    }
    if (i < NOA * C) {
        float v1 = 0.f, v2 = 0.f;
        if (i < 48 * C) { v1 = so1[i]; v2 = so2[i]; }
        else if (i < 72 * C) { v1 = aw1[i - 48 * C]; v2 = aw2[i - 48 * C]; }
        woa[i] = __float2bfloat16(v1);
        woa[NOA * C + i] = __float2bfloat16(v2);
    }
    if (i < NOA) {
        boa[i]       = (i < 48) ? so1b[i] : (i < 72 ? aw1b[i - 48] : 0.f);
        boa[NOA + i] = (i < 48) ? so2b[i] : (i < 72 ? aw2b[i - 48] : 0.f);
    }
}

// ---------------- LayerNorm core ----------------
__device__ __forceinline__ void ln_row(const float* __restrict__ x,
                                       const float* __restrict__ w,
                                       const float* __restrict__ b,
                                       __nv_bfloat16* __restrict__ y, int row) {
    int t = threadIdx.x;
    int lane = t & 31, wid = t >> 5;
    float4 v = ((const float4*)(x + (size_t)row * C))[t];

    __shared__ float part[6];
    float s = v.x + v.y + v.z + v.w;
    #pragma unroll
    for (int o = 16; o; o >>= 1) s += __shfl_down_sync(0xffffffffu, s, o);
    if (!lane) part[wid] = s;
    __syncthreads();
    float mu = (part[0] + part[1] + part[2] + part[3] + part[4] + part[5]) * (1.f / C);

    float dx = v.x - mu, dy = v.y - mu, dz = v.z - mu, dw = v.w - mu;
    s = dx * dx + dy * dy + dz * dz + dw * dw;
    __syncthreads();
    #pragma unroll
    for (int o = 16; o; o >>= 1) s += __shfl_down_sync(0xffffffffu, s, o);
    if (!lane) part[wid] = s;
    __syncthreads();
    float rs = rsqrtf((part[0] + part[1] + part[2] + part[3] + part[4] + part[5]) * (1.f / C) + 1e-6f);

    float4 wv = ((const float4*)w)[t];
    float4 bv = ((const float4*)b)[t];
    __nv_bfloat162 p0 = __floats2bfloat162_rn(dx * rs * wv.x + bv.x, dy * rs * wv.y + bv.y);
    __nv_bfloat162 p1 = __floats2bfloat162_rn(dz * rs * wv.z + bv.z, dw * rs * wv.w + bv.w);
    __nv_bfloat162* yr = (__nv_bfloat162*)(y + (size_t)row * C);
    yr[t * 2] = p0;
    yr[t * 2 + 1] = p1;
}

// 3 tensors in one launch (query, feat, feat2)
__global__ __launch_bounds__(192) void ln_tri(const float* __restrict__ x0,
                                              const float* __restrict__ w0,
                                              const float* __restrict__ b0,
                                              __nv_bfloat16* __restrict__ y0,
                                              const float* __restrict__ x1,
                                              const float* __restrict__ w1,
                                              const float* __restrict__ b1,
                                              __nv_bfloat16* __restrict__ y1,
                                              const float* __restrict__ x2,
                                              const float* __restrict__ w2,
                                              const float* __restrict__ b2,
                                              __nv_bfloat16* __restrict__ y2) {
    int row = blockIdx.x;
    if (row < LQ)          ln_row(x0, w0, b0, y0, row);
    else if (row < 2 * LQ) ln_row(x1, w1, b1, y1, row - LQ);
    else                   ln_row(x2, w2, b2, y2, row - 2 * LQ);
}

__global__ __launch_bounds__(192) void ln_one(const float* __restrict__ x,
                                              const float* __restrict__ w,
                                              const float* __restrict__ b,
                                              __nv_bfloat16* __restrict__ y) {
    ln_row(x, w, b, y, blockIdx.x);
}

// ---------------- bf16 HMMA GEMM core, 64x128x32, 3-stage cp.async -----------
#define MT 64
#define GBN 128
#define GBK 32
#define LDA 40   // elements; 80B row stride (16B aligned, reduces conflicts)
#define NSTG 3
#define SMEM_GEMM (NSTG * (MT + GBN) * LDA * 2)   // 46080 B

__device__ __forceinline__ void mma16816(float* c, const uint32_t* a, const uint32_t* b) {
    asm volatile(
        "mma.sync.aligned.m16n8k16.row.col.f32.bf16.bf16.f32 "
        "{%0,%1,%2,%3}, {%4,%5,%6,%7}, {%8,%9}, {%0,%1,%2,%3};\n"
        : "+f"(c[0]), "+f"(c[1]), "+f"(c[2]), "+f"(c[3])
        : "r"(a[0]), "r"(a[1]), "r"(a[2]), "r"(a[3]), "r"(b[0]), "r"(b[1]));
}

__device__ __forceinline__ void cp16(uint32_t s, const void* g) {
    asm volatile("cp.async.cg.shared.global [%0], [%1], 16;\n" :: "r"(s), "l"(g));
}

// MODE 0: out = acc + bias ; MODE 1: out = resid + gamma*(acc+bias)
template <int MODE, bool OUT_BF16>
__device__ __forceinline__ void gemm_core(const __nv_bfloat16* __restrict__ A,
                                          const __nv_bfloat16* __restrict__ B,
                                          const float* __restrict__ bias,
                                          const float* __restrict__ resid,
                                          const float* __restrict__ gamma,
                                          void* __restrict__ Cout,
                                          int N, int K, int bm, int bn,
                                          __nv_bfloat16* smem) {
    const uint32_t STGB = (MT + GBN) * LDA * 2;   // bytes per stage
    const uint32_t BOFF = MT * LDA * 2;           // B offset within a stage

    int tid = threadIdx.x;
    int warp = tid >> 5, lane = tid & 31;
    int wm = (warp >> 1) * 16;                     // 4 warps along m (16 rows each)
    int wn = (warp & 1) * 64;                      // 2 warps along n

    uint32_t sBase = (uint32_t)__cvta_generic_to_shared(smem);

    uint32_t a_addr[2], b_addr[4][2];
    #pragma unroll
    for (int ks = 0; ks < 2; ks++)
        a_addr[ks] = sBase +
            ((wm + (lane & 15)) * LDA + ks * 16 + (lane >> 4) * 8) * 2;
    #pragma unroll
    for (int pr = 0; pr < 4; pr++)
        #pragma unroll
        for (int ks = 0; ks < 2; ks++)
            b_addr[pr][ks] = sBase + BOFF +
                ((wn + pr * 16 + (lane & 15)) * LDA + ks * 16 + (lane >> 4) * 8) * 2;

    const __nv_bfloat16* Abase = A + (size_t)bm * K;
    const __nv_bfloat16* Bbase = B + (size_t)bn * K;

    auto load_stage = [&](int stage, int k0) {
        uint32_t so = sBase + stage * STGB;
        {   // A: 64 rows * 4 chunks = 256 slots, 1 per thread
            int r = tid >> 2, c = (tid & 3) * 8;
            cp16(so + r * (LDA * 2) + c * 2, Abase + (size_t)r * K + k0 + c);
        }
        #pragma unroll
        for (int i = 0; i < 512; i += 256) {   // B: 128 rows * 4 chunks
            int idx = i + tid;
            int r = idx >> 2, c = (idx & 3) * 8;
            cp16(so + BOFF + r * (LDA * 2) + c * 2, Bbase + (size_t)r * K + k0 + c);
        }
        asm volatile("cp.async.commit_group;\n");
    };

    float acc[8][4] = {};

    const int NK = K / GBK;   // 24
    load_stage(0, 0);
    load_stage(1, GBK);

    for (int it = 0; it < NK; it++) {
        if (it + 1 < NK)
            asm volatile("cp.async.wait_group 1;\n");
        else
            asm volatile("cp.async.wait_group 0;\n");
        __syncthreads();

        if (it + 2 < NK) load_stage((it + 2) % NSTG, (it + 2) * GBK);

        uint32_t soff = (it % NSTG) * STGB;
        #pragma unroll
        for (int ks = 0; ks < 2; ks++) {
            uint32_t af[4], bf[8][2];
            asm volatile("ldmatrix.sync.aligned.m8n8.x4.shared.b16 {%0,%1,%2,%3}, [%4];"
                         : "=r"(af[0]), "=r"(af[1]), "=r"(af[2]), "=r"(af[3])
                         : "r"(a_addr[ks] + soff));
            #pragma unroll
            for (int pr = 0; pr < 4; pr++) {
                uint32_t r0, r1, r2, r3;
                asm volatile("ldmatrix.sync.aligned.m8n8.x4.shared.b16 {%0,%1,%2,%3}, [%4];"
                             : "=r"(r0), "=r"(r1), "=r"(r2), "=r"(r3)
                             : "r"(b_addr[pr][ks] + soff));
                bf[pr * 2 + 0][0] = r0; bf[pr * 2 + 0][1] = r2;
                bf[pr * 2 + 1][0] = r1; bf[pr * 2 + 1][1] = r3;
            }
            #pragma unroll
            for (int na = 0; na < 8; na++)
                mma16816(acc[na], af, bf[na]);
        }
    }

    int tr = lane >> 2, tc = (lane & 3) * 2;
    #pragma unroll
    for (int half = 0; half < 2; half++) {
        int m = bm + wm + half * 8 + tr;
        #pragma unroll
        for (int na = 0; na < 8; na++) {
            int n = bn + wn + na * 8 + tc;
            float v0 = acc[na][half * 2 + 0] + bias[n];
            float v1 = acc[na][half * 2 + 1] + bias[n + 1];
            if (MODE == 1) {
                v0 = resid[(size_t)m * N + n] + gamma[n] * v0;
                v1 = resid[(size_t)m * N + n + 1] + gamma[n + 1] * v1;
            }
            if (OUT_BF16)
                *(__nv_bfloat162*)((__nv_bfloat16*)Cout + (size_t)m * N + n) =
                    __floats2bfloat162_rn(v0, v1);
            else
                *(float2*)((float*)Cout + (size_t)m * N + n) = make_float2(v0, v1);
        }
    }
}

// Fused launch: value-GEMM1 (bx 0..5), value-GEMM2 (bx 6..11), oa-GEMM1 (bx 12)
__global__ __launch_bounds__(256, 3) void gemm_fused3(
    const __nv_bfloat16* __restrict__ A0, const __nv_bfloat16* __restrict__ B0,
    const float* __restrict__ bias0, __nv_bfloat16* __restrict__ out0,
    const __nv_bfloat16* __restrict__ A1, const __nv_bfloat16* __restrict__ B1,
    const float* __restrict__ bias1, __nv_bfloat16* __restrict__ out1,
    const __nv_bfloat16* __restrict__ A2, const __nv_bfloat16* __restrict__ B2,
    const float* __restrict__ bias2, float* __restrict__ out2) {
    extern __shared__ __nv_bfloat16 smem[];
    int bx = blockIdx.x, bm = blockIdx.y * MT;
    if (bx < 6)
        gemm_core<0, true>(A0, B0, bias0, nullptr, nullptr, out0, C, C, bm, bx * GBN, smem);
    else if (bx < 12)
        gemm_core<0, true>(A1, B1, bias1, nullptr, nullptr, out1, C, C, bm, (bx - 6) * GBN, smem);
    else
        gemm_core<0, false>(A2, B2, bias2, nullptr, nullptr, out2, NOA, C, bm, 0, smem);
}

// Standalone GEMM (oa-GEMM2 and the two residual out-GEMMs)
template <int MODE, bool OUT_BF16>
__global__ __launch_bounds__(256, 2) void gemm_bf16(const __nv_bfloat16* __restrict__ A,
                                                    const __nv_bfloat16* __restrict__ B,
                                                    const float* __restrict__ bias,
                                                    const float* __restrict__ resid,
                                                    const float* __restrict__ gamma,
                                                    void* __restrict__ Cout,
                                                    int N, int K) {
    extern __shared__ __nv_bfloat16 smem[];
    gemm_core<MODE, OUT_BF16>(A, B, bias, resid, gamma, Cout, N, K,
                              blockIdx.y * MT, blockIdx.x * GBN, smem);
}

// ---------------- bilinear sampling: 4 ch/thread (uint2), 2 queries/block ----
__device__ __forceinline__ void fetch4(const uint2* __restrict__ val, int y, int x, int t,
                                       float* o) {
    if ((unsigned)y < (unsigned)GRID && (unsigned)x < (unsigned)GRID) {
        uint2 raw = __ldg(&val[(size_t)(y * GRID + x) * (C / 4) + t]);
        __nv_bfloat162 a = *(__nv_bfloat162*)&raw.x;
        __nv_bfloat162 b = *(__nv_bfloat162*)&raw.y;
        o[0] = __bfloat162float(a.x); o[1] = __bfloat162float(a.y);
        o[2] = __bfloat162float(b.x); o[3] = __bfloat162float(b.y);
    } else {
        o[0] = o[1] = o[2] = o[3] = 0.f;
    }
}

__global__ __launch_bounds__(384) void sampler_kernel(const uint2* __restrict__ val,
                                                      const float* __restrict__ ref,
                                                      const float* __restrict__ oa,
                                                      uint2* __restrict__ out) {
    int q0 = blockIdx.x * 2;
    int tid = threadIdx.x;
    __shared__ float s[2][72];
    if (tid < 144) s[tid / 72][tid % 72] = oa[(size_t)(q0 + tid / 72) * NOA + tid % 72];
    __syncthreads();

    int lq = tid / 192;      // 0/1: which query in the pair
    int t = tid % 192;       // channel quad 0..191
    int h = t >> 5;          // head (32 quads = 128 channels)
    int q = q0 + lq;
    const float* sq = s[lq];
    float refx = ref[q * 2];
    float refy = ref[q * 2 + 1];

    float lg[4];
    #pragma unroll
    for (int p = 0; p < NP; p++) lg[p] = sq[48 + h * 4 + p];
    float mx = fmaxf(fmaxf(lg[0], lg[1]), fmaxf(lg[2], lg[3]));
    float e[4];
    float se = 0.f;
    #pragma unroll
    for (int p = 0; p < NP; p++) { e[p] = __expf(lg[p] - mx); se += e[p]; }
    float inv = 1.f / se;

    float acc[4] = {};
    #pragma unroll
    for (int p = 0; p < NP; p++) {
        float px = refx * (float)GRID + sq[(h * 4 + p) * 2]     - 0.5f;
        float py = refy * (float)GRID + sq[(h * 4 + p) * 2 + 1] - 0.5f;
        float fx0 = floorf(px), fy0 = floorf(py);
        int x0 = (int)fx0, y0 = (int)fy0;
        float fx = px - fx0, fy = py - fy0;
        float w00 = (1.f - fy) * (1.f - fx);
        float w01 = (1.f - fy) * fx;
        float w10 = fy * (1.f - fx);
        float w11 = fy * fx;
        float v00[4], v01[4], v10[4], v11[4];
        fetch4(val, y0,     x0,     t, v00);
        fetch4(val, y0,     x0 + 1, t, v01);
        fetch4(val, y0 + 1, x0,     t, v10);
        fetch4(val, y0 + 1, x0 + 1, t, v11);
        float wp = e[p] * inv;
        #pragma unroll
        for (int c = 0; c < 4; c++)
            acc[c] = fmaf(wp, w00 * v00[c] + w01 * v01[c] + w10 * v10[c] + w11 * v11[c],
                          acc[c]);
    }
    uint2 packed;
    __nv_bfloat162 pa = __floats2bfloat162_rn(acc[0], acc[1]);
    __nv_bfloat162 pb = __floats2bfloat162_rn(acc[2], acc[3]);
    packed.x = *(uint32_t*)&pa;
    packed.y = *(uint32_t*)&pb;
    out[(size_t)q * (C / 4) + t] = packed;
}

// ---------------- host side ----------------
extern "C" void kernel_launch(void* const* d_in, const int* in_sizes, int n_in,
                              void* d_out, int out_size) {
    const float* query = (const float*)d_in[0];
    const float* ref   = (const float*)d_in[1];
    const float* feat  = (const float*)d_in[2];
    const float* feat2 = (const float*)d_in[3];
    const float* qn_w = (const float*)d_in[6];
    const float* qn_b = (const float*)d_in[7];
    const float* fn_w = (const float*)d_in[8];
    const float* fn_b = (const float*)d_in[9];
    const float* so_w = (const float*)d_in[10];
    const float* so_b = (const float*)d_in[11];
    const float* aw_w = (const float*)d_in[12];
    const float* aw_b = (const float*)d_in[13];
    const float* vp_w = (const float*)d_in[14];
    const float* vp_b = (const float*)d_in[15];
    const float* op_w = (const float*)d_in[16];
    const float* op_b = (const float*)d_in[17];
    const float* gamma = (const float*)d_in[18];
    const float* qn2_w = (const float*)d_in[19];
    const float* qn2_b = (const float*)d_in[20];
    const float* fn2_w = (const float*)d_in[21];
    const float* fn2_b = (const float*)d_in[22];
    const float* so2_w = (const float*)d_in[23];
    const float* so2_b = (const float*)d_in[24];
    const float* aw2_w = (const float*)d_in[25];
    const float* aw2_b = (const float*)d_in[26];
    const float* vp2_w = (const float*)d_in[27];
    const float* vp2_b = (const float*)d_in[28];
    const float* op2_w = (const float*)d_in[29];
    const float* op2_b = (const float*)d_in[30];
    const float* gamma2 = (const float*)d_in[31];
    float* out = (float*)d_out;

    __nv_bfloat16 *p_qn, *p_fn, *p_fn2, *p_samp, *p_val, *p_val2, *pw_vp, *pw_op, *pw_oa;
    float *p_q1, *p_oa, *pb_oa;
    cudaGetSymbolAddress((void**)&p_qn, s_qn);
    cudaGetSymbolAddress((void**)&p_fn, s_fn);
    cudaGetSymbolAddress((void**)&p_fn2, s_fn2);
    cudaGetSymbolAddress((void**)&p_samp, s_samp);
    cudaGetSymbolAddress((void**)&p_val, s_val);
    cudaGetSymbolAddress((void**)&p_val2, s_val2);
    cudaGetSymbolAddress((void**)&pw_vp, w_vp);
    cudaGetSymbolAddress((void**)&pw_op, w_op);
    cudaGetSymbolAddress((void**)&pw_oa, w_oa);
    cudaGetSymbolAddress((void**)&pb_oa, b_oa);
    cudaGetSymbolAddress((void**)&p_q1, g_q1);
    cudaGetSymbolAddress((void**)&p_oa, g_oa);

    static bool attr_done = false;
    if (!attr_done) {
        cudaFuncSetAttribute(gemm_fused3,
                             cudaFuncAttributeMaxDynamicSharedMemorySize, SMEM_GEMM);
        cudaFuncSetAttribute(gemm_bf16<0, false>,
                             cudaFuncAttributeMaxDynamicSharedMemorySize, SMEM_GEMM);
        cudaFuncSetAttribute(gemm_bf16<1, false>,
                             cudaFuncAttributeMaxDynamicSharedMemorySize, SMEM_GEMM);
        attr_done = true;
    }

    const int nW = C * C;
    prep_weights<<<(nW + 255) / 256, 256>>>(vp_w, op_w, vp2_w, op2_w,
                                            so_w, aw_w, so_b, aw_b,
                                            so2_w, aw2_w, so2_b, aw2_b,
                                            pw_vp, pw_op, pw_oa, pb_oa);

    // All stage-independent LNs up front: LN(query), LN(feat), LN(feat2)
    ln_tri<<<3 * LQ, 192>>>(query, qn_w, qn_b, p_qn,
                            feat, fn_w, fn_b, p_fn,
                            feat2, fn2_w, fn2_b, p_fn2);

    // Fused: value-GEMM1, value-GEMM2 (stage-2 hoisted), oa-GEMM1 — one dense grid
    gemm_fused3<<<dim3(13, LQ / MT), 256, SMEM_GEMM>>>(
        p_fn, pw_vp, vp_b, p_val,
        p_fn2, pw_vp + nW, vp2_b, p_val2,
        p_qn, pw_oa, pb_oa, p_oa);

    // Stage 1 tail
    sampler_kernel<<<LQ / 2, 384>>>((const uint2*)p_val, ref, p_oa, (uint2*)p_samp);
    gemm_bf16<1, false><<<dim3(C / GBN, LQ / MT), 256, SMEM_GEMM>>>(
        p_samp, pw_op, op_b, query, gamma, p_q1, C, C);

    // Stage 2 (val2 already computed)
    ln_one<<<LQ, 192>>>(p_q1, qn2_w, qn2_b, p_qn);
    gemm_bf16<0, false><<<dim3(1, LQ / MT), 256, SMEM_GEMM>>>(
        p_qn, pw_oa + NOA * C, pb_oa + NOA, nullptr, nullptr, p_oa, NOA, C);
    sampler_kernel<<<LQ / 2, 384>>>((const uint2*)p_val2, ref, p_oa, (uint2*)p_samp);
    gemm_bf16<1, false><<<dim3(C / GBN, LQ / MT), 256, SMEM_GEMM>>>(
        p_samp, pw_op + nW, op2_b, p_q1, gamma2, out, C, C);
}

// round 12
// speedup vs baseline: 5.3999x; 1.0789x over previous
#include <cuda_runtime.h>
#include <cuda_bf16.h>
#include <cstdint>

#define LQ 9216
#define C 768
#define NH 6
#define DH 128
#define NP 4
#define GRID 96
#define NOA 128   // padded offset+aw output width (48 offs + 24 logits + 56 pad)

// ---------------- scratch (no allocations allowed) ----------------
__device__ __nv_bfloat16 s_qn[LQ * C];
__device__ __nv_bfloat16 s_fn[LQ * C];
__device__ __nv_bfloat16 s_fn2[LQ * C];
__device__ __nv_bfloat16 s_samp[LQ * C];
__device__ __nv_bfloat16 s_val[LQ * C];
__device__ __nv_bfloat16 s_val2[LQ * C];
__device__ __nv_bfloat16 w_vp[2][C * C];
__device__ __nv_bfloat16 w_op[2][C * C];
__device__ __nv_bfloat16 w_oa[2][NOA * C];
__device__ float b_oa[2][NOA];
__device__ float g_q1[LQ * C];
__device__ float g_oa[LQ * NOA];

// ---------------- fused weight prep (1 launch) ----------------
__global__ void prep_weights(const float* __restrict__ vp1, const float* __restrict__ op1,
                             const float* __restrict__ vp2, const float* __restrict__ op2,
                             const float* __restrict__ so1, const float* __restrict__ aw1,
                             const float* __restrict__ so1b, const float* __restrict__ aw1b,
                             const float* __restrict__ so2, const float* __restrict__ aw2,
                             const float* __restrict__ so2b, const float* __restrict__ aw2b,
                             __nv_bfloat16* __restrict__ wvp, __nv_bfloat16* __restrict__ wop,
                             __nv_bfloat16* __restrict__ woa, float* __restrict__ boa) {
    int i = blockIdx.x * 256 + threadIdx.x;
    const int nW = C * C;
    if (i < nW) {
        wvp[i] = __float2bfloat16(vp1[i]);
        wop[i] = __float2bfloat16(op1[i]);
        wvp[nW + i] = __float2bfloat16(vp2[i]);
        wop[nW + i] = __float2bfloat16(op2[i]);
    }
    if (i < NOA * C) {
        float v1 = 0.f, v2 = 0.f;
        if (i < 48 * C) { v1 = so1[i]; v2 = so2[i]; }
        else if (i < 72 * C) { v1 = aw1[i - 48 * C]; v2 = aw2[i - 48 * C]; }
        woa[i] = __float2bfloat16(v1);
        woa[NOA * C + i] = __float2bfloat16(v2);
    }
    if (i < NOA) {
        boa[i]       = (i < 48) ? so1b[i] : (i < 72 ? aw1b[i - 48] : 0.f);
        boa[NOA + i] = (i < 48) ? so2b[i] : (i < 72 ? aw2b[i - 48] : 0.f);
    }
}

// ---------------- LayerNorm core ----------------
__device__ __forceinline__ void ln_row(const float* __restrict__ x,
                                       const float* __restrict__ w,
                                       const float* __restrict__ b,
                                       __nv_bfloat16* __restrict__ y, int row) {
    int t = threadIdx.x;
    int lane = t & 31, wid = t >> 5;
    float4 v = ((const float4*)(x + (size_t)row * C))[t];

    __shared__ float part[6];
    float s = v.x + v.y + v.z + v.w;
    #pragma unroll
    for (int o = 16; o; o >>= 1) s += __shfl_down_sync(0xffffffffu, s, o);
    if (!lane) part[wid] = s;
    __syncthreads();
    float mu = (part[0] + part[1] + part[2] + part[3] + part[4] + part[5]) * (1.f / C);

    float dx = v.x - mu, dy = v.y - mu, dz = v.z - mu, dw = v.w - mu;
    s = dx * dx + dy * dy + dz * dz + dw * dw;
    __syncthreads();
    #pragma unroll
    for (int o = 16; o; o >>= 1) s += __shfl_down_sync(0xffffffffu, s, o);
    if (!lane) part[wid] = s;
    __syncthreads();
    float rs = rsqrtf((part[0] + part[1] + part[2] + part[3] + part[4] + part[5]) * (1.f / C) + 1e-6f);

    float4 wv = ((const float4*)w)[t];
    float4 bv = ((const float4*)b)[t];
    __nv_bfloat162 p0 = __floats2bfloat162_rn(dx * rs * wv.x + bv.x, dy * rs * wv.y + bv.y);
    __nv_bfloat162 p1 = __floats2bfloat162_rn(dz * rs * wv.z + bv.z, dw * rs * wv.w + bv.w);
    __nv_bfloat162* yr = (__nv_bfloat162*)(y + (size_t)row * C);
    yr[t * 2] = p0;
    yr[t * 2 + 1] = p1;
}

// 3 tensors in one launch (query, feat, feat2)
__global__ __launch_bounds__(192) void ln_tri(const float* __restrict__ x0,
                                              const float* __restrict__ w0,
                                              const float* __restrict__ b0,
                                              __nv_bfloat16* __restrict__ y0,
                                              const float* __restrict__ x1,
                                              const float* __restrict__ w1,
                                              const float* __restrict__ b1,
                                              __nv_bfloat16* __restrict__ y1,
                                              const float* __restrict__ x2,
                                              const float* __restrict__ w2,
                                              const float* __restrict__ b2,
                                              __nv_bfloat16* __restrict__ y2) {
    int row = blockIdx.x;
    if (row < LQ)          ln_row(x0, w0, b0, y0, row);
    else if (row < 2 * LQ) ln_row(x1, w1, b1, y1, row - LQ);
    else                   ln_row(x2, w2, b2, y2, row - 2 * LQ);
}

__global__ __launch_bounds__(192) void ln_one(const float* __restrict__ x,
                                              const float* __restrict__ w,
                                              const float* __restrict__ b,
                                              __nv_bfloat16* __restrict__ y) {
    ln_row(x, w, b, y, blockIdx.x);
}

// ---------------- bf16 HMMA GEMM core, 64x128x32, 3-stage cp.async -----------
#define MT 64
#define GBN 128
#define GBK 32
#define LDA 40   // elements; 80B row stride (16B aligned, reduces conflicts)
#define NSTG 3
#define SMEM_GEMM (NSTG * (MT + GBN) * LDA * 2)   // 46080 B

__device__ __forceinline__ void mma16816(float* c, const uint32_t* a, const uint32_t* b) {
    asm volatile(
        "mma.sync.aligned.m16n8k16.row.col.f32.bf16.bf16.f32 "
        "{%0,%1,%2,%3}, {%4,%5,%6,%7}, {%8,%9}, {%0,%1,%2,%3};\n"
        : "+f"(c[0]), "+f"(c[1]), "+f"(c[2]), "+f"(c[3])
        : "r"(a[0]), "r"(a[1]), "r"(a[2]), "r"(a[3]), "r"(b[0]), "r"(b[1]));
}

__device__ __forceinline__ void cp16(uint32_t s, const void* g) {
    asm volatile("cp.async.cg.shared.global [%0], [%1], 16;\n" :: "r"(s), "l"(g));
}

// MODE 0: out = acc + bias ; MODE 1: out = resid + gamma*(acc+bias)
template <int MODE, bool OUT_BF16>
__device__ __forceinline__ void gemm_core(const __nv_bfloat16* __restrict__ A,
                                          const __nv_bfloat16* __restrict__ B,
                                          const float* __restrict__ bias,
                                          const float* __restrict__ resid,
                                          const float* __restrict__ gamma,
                                          void* __restrict__ Cout,
                                          int N, int K, int bm, int bn,
                                          __nv_bfloat16* smem) {
    const uint32_t STGB = (MT + GBN) * LDA * 2;   // bytes per stage
    const uint32_t BOFF = MT * LDA * 2;           // B offset within a stage

    int tid = threadIdx.x;
    int warp = tid >> 5, lane = tid & 31;
    int wm = (warp >> 1) * 16;                     // 4 warps along m (16 rows each)
    int wn = (warp & 1) * 64;                      // 2 warps along n

    uint32_t sBase = (uint32_t)__cvta_generic_to_shared(smem);

    uint32_t a_addr[2], b_addr[4][2];
    #pragma unroll
    for (int ks = 0; ks < 2; ks++)
        a_addr[ks] = sBase +
            ((wm + (lane & 15)) * LDA + ks * 16 + (lane >> 4) * 8) * 2;
    #pragma unroll
    for (int pr = 0; pr < 4; pr++)
        #pragma unroll
        for (int ks = 0; ks < 2; ks++)
            b_addr[pr][ks] = sBase + BOFF +
                ((wn + pr * 16 + (lane & 15)) * LDA + ks * 16 + (lane >> 4) * 8) * 2;

    const __nv_bfloat16* Abase = A + (size_t)bm * K;
    const __nv_bfloat16* Bbase = B + (size_t)bn * K;

    auto load_stage = [&](int stage, int k0) {
        uint32_t so = sBase + stage * STGB;
        {   // A: 64 rows * 4 chunks = 256 slots, 1 per thread
            int r = tid >> 2, c = (tid & 3) * 8;
            cp16(so + r * (LDA * 2) + c * 2, Abase + (size_t)r * K + k0 + c);
        }
        #pragma unroll
        for (int i = 0; i < 512; i += 256) {   // B: 128 rows * 4 chunks
            int idx = i + tid;
            int r = idx >> 2, c = (idx & 3) * 8;
            cp16(so + BOFF + r * (LDA * 2) + c * 2, Bbase + (size_t)r * K + k0 + c);
        }
        asm volatile("cp.async.commit_group;\n");
    };

    float acc[8][4] = {};

    const int NK = K / GBK;   // 24
    load_stage(0, 0);
    load_stage(1, GBK);

    for (int it = 0; it < NK; it++) {
        if (it + 1 < NK)
            asm volatile("cp.async.wait_group 1;\n");
        else
            asm volatile("cp.async.wait_group 0;\n");
        __syncthreads();

        if (it + 2 < NK) load_stage((it + 2) % NSTG, (it + 2) * GBK);

        uint32_t soff = (it % NSTG) * STGB;
        #pragma unroll
        for (int ks = 0; ks < 2; ks++) {
            uint32_t af[4], bf[8][2];
            asm volatile("ldmatrix.sync.aligned.m8n8.x4.shared.b16 {%0,%1,%2,%3}, [%4];"
                         : "=r"(af[0]), "=r"(af[1]), "=r"(af[2]), "=r"(af[3])
                         : "r"(a_addr[ks] + soff));
            #pragma unroll
            for (int pr = 0; pr < 4; pr++) {
                uint32_t r0, r1, r2, r3;
                asm volatile("ldmatrix.sync.aligned.m8n8.x4.shared.b16 {%0,%1,%2,%3}, [%4];"
                             : "=r"(r0), "=r"(r1), "=r"(r2), "=r"(r3)
                             : "r"(b_addr[pr][ks] + soff));
                bf[pr * 2 + 0][0] = r0; bf[pr * 2 + 0][1] = r2;
                bf[pr * 2 + 1][0] = r1; bf[pr * 2 + 1][1] = r3;
            }
            #pragma unroll
            for (int na = 0; na < 8; na++)
                mma16816(acc[na], af, bf[na]);
        }
    }

    int tr = lane >> 2, tc = (lane & 3) * 2;
    #pragma unroll
    for (int half = 0; half < 2; half++) {
        int m = bm + wm + half * 8 + tr;
        #pragma unroll
        for (int na = 0; na < 8; na++) {
            int n = bn + wn + na * 8 + tc;
            float v0 = acc[na][half * 2 + 0] + bias[n];
            float v1 = acc[na][half * 2 + 1] + bias[n + 1];
            if (MODE == 1) {
                v0 = resid[(size_t)m * N + n] + gamma[n] * v0;
                v1 = resid[(size_t)m * N + n + 1] + gamma[n + 1] * v1;
            }
            if (OUT_BF16)
                *(__nv_bfloat162*)((__nv_bfloat16*)Cout + (size_t)m * N + n) =
                    __floats2bfloat162_rn(v0, v1);
            else
                *(float2*)((float*)Cout + (size_t)m * N + n) = make_float2(v0, v1);
        }
    }
}

// Fused launch: value-GEMM1 (bx 0..5), value-GEMM2 (bx 6..11), oa-GEMM1 (bx 12)
__global__ __launch_bounds__(256, 3) void gemm_fused3(
    const __nv_bfloat16* __restrict__ A0, const __nv_bfloat16* __restrict__ B0,
    const float* __restrict__ bias0, __nv_bfloat16* __restrict__ out0,
    const __nv_bfloat16* __restrict__ A1, const __nv_bfloat16* __restrict__ B1,
    const float* __restrict__ bias1, __nv_bfloat16* __restrict__ out1,
    const __nv_bfloat16* __restrict__ A2, const __nv_bfloat16* __restrict__ B2,
    const float* __restrict__ bias2, float* __restrict__ out2) {
    extern __shared__ __nv_bfloat16 smem[];
    int bx = blockIdx.x, bm = blockIdx.y * MT;
    if (bx < 6)
        gemm_core<0, true>(A0, B0, bias0, nullptr, nullptr, out0, C, C, bm, bx * GBN, smem);
    else if (bx < 12)
        gemm_core<0, true>(A1, B1, bias1, nullptr, nullptr, out1, C, C, bm, (bx - 6) * GBN, smem);
    else
        gemm_core<0, false>(A2, B2, bias2, nullptr, nullptr, out2, NOA, C, bm, 0, smem);
}

// Standalone GEMM (oa-GEMM2 and the two residual out-GEMMs)
template <int MODE, bool OUT_BF16>
__global__ __launch_bounds__(256, 3) void gemm_bf16(const __nv_bfloat16* __restrict__ A,
                                                    const __nv_bfloat16* __restrict__ B,
                                                    const float* __restrict__ bias,
                                                    const float* __restrict__ resid,
                                                    const float* __restrict__ gamma,
                                                    void* __restrict__ Cout,
                                                    int N, int K) {
    extern __shared__ __nv_bfloat16 smem[];
    gemm_core<MODE, OUT_BF16>(A, B, bias, resid, gamma, Cout, N, K,
                              blockIdx.y * MT, blockIdx.x * GBN, smem);
}

// ---------------- bilinear sampling with per-block precompute ----------------
// Block = 2 queries, 384 threads. Phase 1: 48 threads compute softmax-folded
// bilinear weights (validity folded in: weight=0 OOB, index clamped) + corner
// offsets. Phase 2: each thread does 4 unconditional 8B gathers per point.
__global__ __launch_bounds__(384) void sampler_kernel(const uint2* __restrict__ val,
                                                      const float* __restrict__ ref,
                                                      const float* __restrict__ oa,
                                                      uint2* __restrict__ out) {
    int q0 = blockIdx.x * 2;
    int tid = threadIdx.x;
    __shared__ float s[2][72];
    __shared__ float pw[48][4];   // weights (wp-folded) for 4 corners
    __shared__ int   po[48][4];   // clamped corner offsets (uint2 units)
    if (tid < 144) s[tid / 72][tid % 72] = oa[(size_t)(q0 + tid / 72) * NOA + tid % 72];
    __syncthreads();

    if (tid < 48) {
        int lq = tid / 24, hp = tid % 24;
        int h = hp >> 2, p = hp & 3;
        const float* sq = s[lq];
        int q = q0 + lq;

        float lg0 = sq[48 + h * 4 + 0], lg1 = sq[48 + h * 4 + 1];
        float lg2 = sq[48 + h * 4 + 2], lg3 = sq[48 + h * 4 + 3];
        float mx = fmaxf(fmaxf(lg0, lg1), fmaxf(lg2, lg3));
        float se = __expf(lg0 - mx) + __expf(lg1 - mx) + __expf(lg2 - mx) + __expf(lg3 - mx);
        float wp = __expf(sq[48 + h * 4 + p] - mx) / se;

        float px = ref[q * 2]     * (float)GRID + sq[(h * 4 + p) * 2]     - 0.5f;
        float py = ref[q * 2 + 1] * (float)GRID + sq[(h * 4 + p) * 2 + 1] - 0.5f;
        float fx0 = floorf(px), fy0 = floorf(py);
        int x0 = (int)fx0, y0 = (int)fy0;
        float fx = px - fx0, fy = py - fy0;

        float vx0 = ((unsigned)x0 < (unsigned)GRID) ? 1.f : 0.f;
        float vx1 = ((unsigned)(x0 + 1) < (unsigned)GRID) ? 1.f : 0.f;
        float vy0 = ((unsigned)y0 < (unsigned)GRID) ? 1.f : 0.f;
        float vy1 = ((unsigned)(y0 + 1) < (unsigned)GRID) ? 1.f : 0.f;
        pw[tid][0] = wp * (1.f - fy) * (1.f - fx) * vy0 * vx0;
        pw[tid][1] = wp * (1.f - fy) * fx         * vy0 * vx1;
        pw[tid][2] = wp * fy         * (1.f - fx) * vy1 * vx0;
        pw[tid][3] = wp * fy         * fx         * vy1 * vx1;

        int x0c = min(GRID - 1, max(0, x0)), x1c = min(GRID - 1, max(0, x0 + 1));
        int y0c = min(GRID - 1, max(0, y0)), y1c = min(GRID - 1, max(0, y0 + 1));
        po[tid][0] = (y0c * GRID + x0c) * (C / 4);
        po[tid][1] = (y0c * GRID + x1c) * (C / 4);
        po[tid][2] = (y1c * GRID + x0c) * (C / 4);
        po[tid][3] = (y1c * GRID + x1c) * (C / 4);
    }
    __syncthreads();

    int lq = tid / 192;      // which query in the pair
    int t = tid % 192;       // channel quad 0..191
    int h = t >> 5;          // head
    int q = q0 + lq;
    int base = lq * 24 + h * 4;

    float acc[4] = {};
    #pragma unroll
    for (int p = 0; p < NP; p++) {
        float4 w = *(const float4*)pw[base + p];
        int4 o4 = *(const int4*)po[base + p];
        uint2 r00 = __ldg(&val[o4.x + t]);
        uint2 r01 = __ldg(&val[o4.y + t]);
        uint2 r10 = __ldg(&val[o4.z + t]);
        uint2 r11 = __ldg(&val[o4.w + t]);
        #pragma unroll
        for (int half = 0; half < 2; half++) {
            __nv_bfloat162 b00 = *(__nv_bfloat162*)(half ? &r00.y : &r00.x);
            __nv_bfloat162 b01 = *(__nv_bfloat162*)(half ? &r01.y : &r01.x);
            __nv_bfloat162 b10 = *(__nv_bfloat162*)(half ? &r10.y : &r10.x);
            __nv_bfloat162 b11 = *(__nv_bfloat162*)(half ? &r11.y : &r11.x);
            acc[half * 2 + 0] = fmaf(w.x, __bfloat162float(b00.x),
                                fmaf(w.y, __bfloat162float(b01.x),
                                fmaf(w.z, __bfloat162float(b10.x),
                                fmaf(w.w, __bfloat162float(b11.x), acc[half * 2 + 0]))));
            acc[half * 2 + 1] = fmaf(w.x, __bfloat162float(b00.y),
                                fmaf(w.y, __bfloat162float(b01.y),
                                fmaf(w.z, __bfloat162float(b10.y),
                                fmaf(w.w, __bfloat162float(b11.y), acc[half * 2 + 1]))));
        }
    }
    uint2 packed;
    __nv_bfloat162 pa = __floats2bfloat162_rn(acc[0], acc[1]);
    __nv_bfloat162 pb = __floats2bfloat162_rn(acc[2], acc[3]);
    packed.x = *(uint32_t*)&pa;
    packed.y = *(uint32_t*)&pb;
    out[(size_t)q * (C / 4) + t] = packed;
}

// ---------------- host side ----------------
extern "C" void kernel_launch(void* const* d_in, const int* in_sizes, int n_in,
                              void* d_out, int out_size) {
    const float* query = (const float*)d_in[0];
    const float* ref   = (const float*)d_in[1];
    const float* feat  = (const float*)d_in[2];
    const float* feat2 = (const float*)d_in[3];
    const float* qn_w = (const float*)d_in[6];
    const float* qn_b = (const float*)d_in[7];
    const float* fn_w = (const float*)d_in[8];
    const float* fn_b = (const float*)d_in[9];
    const float* so_w = (const float*)d_in[10];
    const float* so_b = (const float*)d_in[11];
    const float* aw_w = (const float*)d_in[12];
    const float* aw_b = (const float*)d_in[13];
    const float* vp_w = (const float*)d_in[14];
    const float* vp_b = (const float*)d_in[15];
    const float* op_w = (const float*)d_in[16];
    const float* op_b = (const float*)d_in[17];
    const float* gamma = (const float*)d_in[18];
    const float* qn2_w = (const float*)d_in[19];
    const float* qn2_b = (const float*)d_in[20];
    const float* fn2_w = (const float*)d_in[21];
    const float* fn2_b = (const float*)d_in[22];
    const float* so2_w = (const float*)d_in[23];
    const float* so2_b = (const float*)d_in[24];
    const float* aw2_w = (const float*)d_in[25];
    const float* aw2_b = (const float*)d_in[26];
    const float* vp2_w = (const float*)d_in[27];
    const float* vp2_b = (const float*)d_in[28];
    const float* op2_w = (const float*)d_in[29];
    const float* op2_b = (const float*)d_in[30];
    const float* gamma2 = (const float*)d_in[31];
    float* out = (float*)d_out;

    __nv_bfloat16 *p_qn, *p_fn, *p_fn2, *p_samp, *p_val, *p_val2, *pw_vp, *pw_op, *pw_oa;
    float *p_q1, *p_oa, *pb_oa;
    cudaGetSymbolAddress((void**)&p_qn, s_qn);
    cudaGetSymbolAddress((void**)&p_fn, s_fn);
    cudaGetSymbolAddress((void**)&p_fn2, s_fn2);
    cudaGetSymbolAddress((void**)&p_samp, s_samp);
    cudaGetSymbolAddress((void**)&p_val, s_val);
    cudaGetSymbolAddress((void**)&p_val2, s_val2);
    cudaGetSymbolAddress((void**)&pw_vp, w_vp);
    cudaGetSymbolAddress((void**)&pw_op, w_op);
    cudaGetSymbolAddress((void**)&pw_oa, w_oa);
    cudaGetSymbolAddress((void**)&pb_oa, b_oa);
    cudaGetSymbolAddress((void**)&p_q1, g_q1);
    cudaGetSymbolAddress((void**)&p_oa, g_oa);

    static bool attr_done = false;
    if (!attr_done) {
        cudaFuncSetAttribute(gemm_fused3,
                             cudaFuncAttributeMaxDynamicSharedMemorySize, SMEM_GEMM);
        cudaFuncSetAttribute(gemm_bf16<0, false>,
                             cudaFuncAttributeMaxDynamicSharedMemorySize, SMEM_GEMM);
        cudaFuncSetAttribute(gemm_bf16<1, false>,
                             cudaFuncAttributeMaxDynamicSharedMemorySize, SMEM_GEMM);
        attr_done = true;
    }

    const int nW = C * C;
    prep_weights<<<(nW + 255) / 256, 256>>>(vp_w, op_w, vp2_w, op2_w,
                                            so_w, aw_w, so_b, aw_b,
                                            so2_w, aw2_w, so2_b, aw2_b,
                                            pw_vp, pw_op, pw_oa, pb_oa);

    // All stage-independent LNs up front: LN(query), LN(feat), LN(feat2)
    ln_tri<<<3 * LQ, 192>>>(query, qn_w, qn_b, p_qn,
                            feat, fn_w, fn_b, p_fn,
                            feat2, fn2_w, fn2_b, p_fn2);

    // Fused: value-GEMM1, value-GEMM2 (stage-2 hoisted), oa-GEMM1 — one dense grid
    gemm_fused3<<<dim3(13, LQ / MT), 256, SMEM_GEMM>>>(
        p_fn, pw_vp, vp_b, p_val,
        p_fn2, pw_vp + nW, vp2_b, p_val2,
        p_qn, pw_oa, pb_oa, p_oa);

    // Stage 1 tail
    sampler_kernel<<<LQ / 2, 384>>>((const uint2*)p_val, ref, p_oa, (uint2*)p_samp);
    gemm_bf16<1, false><<<dim3(C / GBN, LQ / MT), 256, SMEM_GEMM>>>(
        p_samp, pw_op, op_b, query, gamma, p_q1, C, C);

    // Stage 2 (val2 already computed)
    ln_one<<<LQ, 192>>>(p_q1, qn2_w, qn2_b, p_qn);
    gemm_bf16<0, false><<<dim3(1, LQ / MT), 256, SMEM_GEMM>>>(
        p_qn, pw_oa + NOA * C, pb_oa + NOA, nullptr, nullptr, p_oa, NOA, C);
    sampler_kernel<<<LQ / 2, 384>>>((const uint2*)p_val2, ref, p_oa, (uint2*)p_samp);
    gemm_bf16<1, false><<<dim3(C / GBN, LQ / MT), 256, SMEM_GEMM>>>(
        p_samp, pw_op + nW, op2_b, p_q1, gamma2, out, C, C);
}

// round 13
// speedup vs baseline: 5.4975x; 1.0181x over previous
#include <cuda_runtime.h>
#include <cuda_bf16.h>
#include <cstdint>

#define LQ 9216
#define C 768
#define NH 6
#define DH 128
#define NP 4
#define GRID 96
#define NOA 128   // padded offset+aw output width (48 offs + 24 logits + 56 pad)

// ---------------- scratch (no allocations allowed) ----------------
__device__ __nv_bfloat16 s_qn[LQ * C];
__device__ __nv_bfloat16 s_fn[LQ * C];
__device__ __nv_bfloat16 s_fn2[LQ * C];
__device__ __nv_bfloat16 s_samp[LQ * C];
__device__ __nv_bfloat16 s_val[LQ * C];
__device__ __nv_bfloat16 s_val2[LQ * C];
__device__ __nv_bfloat16 w_vp[2][C * C];
__device__ __nv_bfloat16 w_op[2][C * C];
__device__ __nv_bfloat16 w_oa[2][NOA * C];
__device__ float b_oa[2][NOA];
__device__ float g_q1[LQ * C];
__device__ float g_oa[LQ * NOA];

// ---------------- fused weight prep (1 launch) ----------------
__global__ void prep_weights(const float* __restrict__ vp1, const float* __restrict__ op1,
                             const float* __restrict__ vp2, const float* __restrict__ op2,
                             const float* __restrict__ so1, const float* __restrict__ aw1,
                             const float* __restrict__ so1b, const float* __restrict__ aw1b,
                             const float* __restrict__ so2, const float* __restrict__ aw2,
                             const float* __restrict__ so2b, const float* __restrict__ aw2b,
                             __nv_bfloat16* __restrict__ wvp, __nv_bfloat16* __restrict__ wop,
                             __nv_bfloat16* __restrict__ woa, float* __restrict__ boa) {
    int i = blockIdx.x * 256 + threadIdx.x;
    const int nW = C * C;
    if (i < nW) {
        wvp[i] = __float2bfloat16(vp1[i]);
        wop[i] = __float2bfloat16(op1[i]);
        wvp[nW + i] = __float2bfloat16(vp2[i]);
        wop[nW + i] = __float2bfloat16(op2[i]);
    }
    if (i < NOA * C) {
        float v1 = 0.f, v2 = 0.f;
        if (i < 48 * C) { v1 = so1[i]; v2 = so2[i]; }
        else if (i < 72 * C) { v1 = aw1[i - 48 * C]; v2 = aw2[i - 48 * C]; }
        woa[i] = __float2bfloat16(v1);
        woa[NOA * C + i] = __float2bfloat16(v2);
    }
    if (i < NOA) {
        boa[i]       = (i < 48) ? so1b[i] : (i < 72 ? aw1b[i - 48] : 0.f);
        boa[NOA + i] = (i < 48) ? so2b[i] : (i < 72 ? aw2b[i - 48] : 0.f);
    }
}

// ---------------- LayerNorm core ----------------
__device__ __forceinline__ void ln_row(const float* __restrict__ x,
                                       const float* __restrict__ w,
                                       const float* __restrict__ b,
                                       __nv_bfloat16* __restrict__ y, int row) {
    int t = threadIdx.x;
    int lane = t & 31, wid = t >> 5;
    float4 v = ((const float4*)(x + (size_t)row * C))[t];

    __shared__ float part[6];
    float s = v.x + v.y + v.z + v.w;
    #pragma unroll
    for (int o = 16; o; o >>= 1) s += __shfl_down_sync(0xffffffffu, s, o);
    if (!lane) part[wid] = s;
    __syncthreads();
    float mu = (part[0] + part[1] + part[2] + part[3] + part[4] + part[5]) * (1.f / C);

    float dx = v.x - mu, dy = v.y - mu, dz = v.z - mu, dw = v.w - mu;
    s = dx * dx + dy * dy + dz * dz + dw * dw;
    __syncthreads();
    #pragma unroll
    for (int o = 16; o; o >>= 1) s += __shfl_down_sync(0xffffffffu, s, o);
    if (!lane) part[wid] = s;
    __syncthreads();
    float rs = rsqrtf((part[0] + part[1] + part[2] + part[3] + part[4] + part[5]) * (1.f / C) + 1e-6f);

    float4 wv = ((const float4*)w)[t];
    float4 bv = ((const float4*)b)[t];
    __nv_bfloat162 p0 = __floats2bfloat162_rn(dx * rs * wv.x + bv.x, dy * rs * wv.y + bv.y);
    __nv_bfloat162 p1 = __floats2bfloat162_rn(dz * rs * wv.z + bv.z, dw * rs * wv.w + bv.w);
    __nv_bfloat162* yr = (__nv_bfloat162*)(y + (size_t)row * C);
    yr[t * 2] = p0;
    yr[t * 2 + 1] = p1;
}

// 3 tensors in one launch (query, feat, feat2)
__global__ __launch_bounds__(192) void ln_tri(const float* __restrict__ x0,
                                              const float* __restrict__ w0,
                                              const float* __restrict__ b0,
                                              __nv_bfloat16* __restrict__ y0,
                                              const float* __restrict__ x1,
                                              const float* __restrict__ w1,
                                              const float* __restrict__ b1,
                                              __nv_bfloat16* __restrict__ y1,
                                              const float* __restrict__ x2,
                                              const float* __restrict__ w2,
                                              const float* __restrict__ b2,
                                              __nv_bfloat16* __restrict__ y2) {
    int row = blockIdx.x;
    if (row < LQ)          ln_row(x0, w0, b0, y0, row);
    else if (row < 2 * LQ) ln_row(x1, w1, b1, y1, row - LQ);
    else                   ln_row(x2, w2, b2, y2, row - 2 * LQ);
}

__global__ __launch_bounds__(192) void ln_one(const float* __restrict__ x,
                                              const float* __restrict__ w,
                                              const float* __restrict__ b,
                                              __nv_bfloat16* __restrict__ y) {
    ln_row(x, w, b, y, blockIdx.x);
}

// ---------------- bf16 HMMA GEMM core, 64xNTx32, 3-stage cp.async ------------
#define MT 64
#define GBN 128
#define GBK 32
#define LDA 40   // elements; 80B row stride (16B aligned, reduces conflicts)
#define NSTG 3
#define SMEM_GEMM (NSTG * (MT + GBN) * LDA * 2)   // 46080 B

__device__ __forceinline__ void mma16816(float* c, const uint32_t* a, const uint32_t* b) {
    asm volatile(
        "mma.sync.aligned.m16n8k16.row.col.f32.bf16.bf16.f32 "
        "{%0,%1,%2,%3}, {%4,%5,%6,%7}, {%8,%9}, {%0,%1,%2,%3};\n"
        : "+f"(c[0]), "+f"(c[1]), "+f"(c[2]), "+f"(c[3])
        : "r"(a[0]), "r"(a[1]), "r"(a[2]), "r"(a[3]), "r"(b[0]), "r"(b[1]));
}

__device__ __forceinline__ void cp16(uint32_t s, const void* g) {
    asm volatile("cp.async.cg.shared.global [%0], [%1], 16;\n" :: "r"(s), "l"(g));
}

// MODE 0: out = acc + bias ; MODE 1: out = resid + gamma*(acc+bias)
// NT: n-tile width (128 or 64)
template <int MODE, bool OUT_BF16, int NT>
__device__ __forceinline__ void gemm_core(const __nv_bfloat16* __restrict__ A,
                                          const __nv_bfloat16* __restrict__ B,
                                          const float* __restrict__ bias,
                                          const float* __restrict__ resid,
                                          const float* __restrict__ gamma,
                                          void* __restrict__ Cout,
                                          int N, int K, int bm, int bn,
                                          __nv_bfloat16* smem) {
    const uint32_t STGB = (MT + NT) * LDA * 2;    // bytes per stage
    const uint32_t BOFF = MT * LDA * 2;           // B offset within a stage
    constexpr int NPR = NT / 32;                  // x4-ldmatrix loads for B
    constexpr int NA = NT / 16;                   // n8 MMA tiles per warp

    int tid = threadIdx.x;
    int warp = tid >> 5, lane = tid & 31;
    int wm = (warp >> 1) * 16;                     // 4 warps along m (16 rows each)
    int wn = (warp & 1) * (NT / 2);                // 2 warps along n

    uint32_t sBase = (uint32_t)__cvta_generic_to_shared(smem);

    uint32_t a_addr[2], b_addr[NPR][2];
    #pragma unroll
    for (int ks = 0; ks < 2; ks++)
        a_addr[ks] = sBase +
            ((wm + (lane & 15)) * LDA + ks * 16 + (lane >> 4) * 8) * 2;
    #pragma unroll
    for (int pr = 0; pr < NPR; pr++)
        #pragma unroll
        for (int ks = 0; ks < 2; ks++)
            b_addr[pr][ks] = sBase + BOFF +
                ((wn + pr * 16 + (lane & 15)) * LDA + ks * 16 + (lane >> 4) * 8) * 2;

    const __nv_bfloat16* Abase = A + (size_t)bm * K;
    const __nv_bfloat16* Bbase = B + (size_t)bn * K;

    auto load_stage = [&](int stage, int k0) {
        uint32_t so = sBase + stage * STGB;
        {   // A: 64 rows * 4 chunks = 256 slots, 1 per thread
            int r = tid >> 2, c = (tid & 3) * 8;
            cp16(so + r * (LDA * 2) + c * 2, Abase + (size_t)r * K + k0 + c);
        }
        #pragma unroll
        for (int i = 0; i < NT * 4; i += 256) {   // B: NT rows * 4 chunks
            int idx = i + tid;
            int r = idx >> 2, c = (idx & 3) * 8;
            cp16(so + BOFF + r * (LDA * 2) + c * 2, Bbase + (size_t)r * K + k0 + c);
        }
        asm volatile("cp.async.commit_group;\n");
    };

    float acc[NA][4] = {};

    const int NK = K / GBK;   // 24
    load_stage(0, 0);
    load_stage(1, GBK);

    for (int it = 0; it < NK; it++) {
        if (it + 1 < NK)
            asm volatile("cp.async.wait_group 1;\n");
        else
            asm volatile("cp.async.wait_group 0;\n");
        __syncthreads();

        if (it + 2 < NK) load_stage((it + 2) % NSTG, (it + 2) * GBK);

        uint32_t soff = (it % NSTG) * STGB;
        #pragma unroll
        for (int ks = 0; ks < 2; ks++) {
            uint32_t af[4], bf[NA][2];
            asm volatile("ldmatrix.sync.aligned.m8n8.x4.shared.b16 {%0,%1,%2,%3}, [%4];"
                         : "=r"(af[0]), "=r"(af[1]), "=r"(af[2]), "=r"(af[3])
                         : "r"(a_addr[ks] + soff));
            #pragma unroll
            for (int pr = 0; pr < NPR; pr++) {
                uint32_t r0, r1, r2, r3;
                asm volatile("ldmatrix.sync.aligned.m8n8.x4.shared.b16 {%0,%1,%2,%3}, [%4];"
                             : "=r"(r0), "=r"(r1), "=r"(r2), "=r"(r3)
                             : "r"(b_addr[pr][ks] + soff));
                bf[pr * 2 + 0][0] = r0; bf[pr * 2 + 0][1] = r2;
                bf[pr * 2 + 1][0] = r1; bf[pr * 2 + 1][1] = r3;
            }
            #pragma unroll
            for (int na = 0; na < NA; na++)
                mma16816(acc[na], af, bf[na]);
        }
    }

    int tr = lane >> 2, tc = (lane & 3) * 2;
    #pragma unroll
    for (int half = 0; half < 2; half++) {
        int m = bm + wm + half * 8 + tr;
        #pragma unroll
        for (int na = 0; na < NA; na++) {
            int n = bn + wn + na * 8 + tc;
            float v0 = acc[na][half * 2 + 0] + bias[n];
            float v1 = acc[na][half * 2 + 1] + bias[n + 1];
            if (MODE == 1) {
                v0 = resid[(size_t)m * N + n] + gamma[n] * v0;
                v1 = resid[(size_t)m * N + n + 1] + gamma[n + 1] * v1;
            }
            if (OUT_BF16)
                *(__nv_bfloat162*)((__nv_bfloat16*)Cout + (size_t)m * N + n) =
                    __floats2bfloat162_rn(v0, v1);
            else
                *(float2*)((float*)Cout + (size_t)m * N + n) = make_float2(v0, v1);
        }
    }
}

// Fused: value-GEMM1 (bx 0..5), value-GEMM2 (bx 6..11), oa-GEMM1 (bx 12..13, NT=64)
__global__ __launch_bounds__(256, 3) void gemm_fused3(
    const __nv_bfloat16* __restrict__ A0, const __nv_bfloat16* __restrict__ B0,
    const float* __restrict__ bias0, __nv_bfloat16* __restrict__ out0,
    const __nv_bfloat16* __restrict__ A1, const __nv_bfloat16* __restrict__ B1,
    const float* __restrict__ bias1, __nv_bfloat16* __restrict__ out1,
    const __nv_bfloat16* __restrict__ A2, const __nv_bfloat16* __restrict__ B2,
    const float* __restrict__ bias2, float* __restrict__ out2) {
    extern __shared__ __nv_bfloat16 smem[];
    int bx = blockIdx.x, bm = blockIdx.y * MT;
    if (bx < 6)
        gemm_core<0, true, 128>(A0, B0, bias0, nullptr, nullptr, out0, C, C, bm, bx * GBN, smem);
    else if (bx < 12)
        gemm_core<0, true, 128>(A1, B1, bias1, nullptr, nullptr, out1, C, C, bm, (bx - 6) * GBN, smem);
    else
        gemm_core<0, false, 64>(A2, B2, bias2, nullptr, nullptr, out2, NOA, C, bm, (bx - 12) * 64, smem);
}

// Standalone out-GEMMs (NT=128) and oa-GEMM2 (NT=64)
template <int MODE, bool OUT_BF16>
__global__ __launch_bounds__(256, 3) void gemm_bf16(const __nv_bfloat16* __restrict__ A,
                                                    const __nv_bfloat16* __restrict__ B,
                                                    const float* __restrict__ bias,
                                                    const float* __restrict__ resid,
                                                    const float* __restrict__ gamma,
                                                    void* __restrict__ Cout,
                                                    int N, int K) {
    extern __shared__ __nv_bfloat16 smem[];
    gemm_core<MODE, OUT_BF16, 128>(A, B, bias, resid, gamma, Cout, N, K,
                                   blockIdx.y * MT, blockIdx.x * GBN, smem);
}

__global__ __launch_bounds__(256, 3) void gemm_oa(const __nv_bfloat16* __restrict__ A,
                                                  const __nv_bfloat16* __restrict__ B,
                                                  const float* __restrict__ bias,
                                                  float* __restrict__ Cout) {
    extern __shared__ __nv_bfloat16 smem[];
    gemm_core<0, false, 64>(A, B, bias, nullptr, nullptr, Cout, NOA, C,
                            blockIdx.y * MT, blockIdx.x * 64, smem);
}

// ---------------- bilinear sampling: uint4 gathers, 8 ch/thread --------------
// Block = 4 queries, 384 threads. Phase 1: 96 threads compute softmax-folded
// bilinear weights (validity folded: weight=0 OOB, clamped index) + offsets.
// Phase 2: each thread handles 8 channels via 16B loads.
__device__ __forceinline__ void accum8(float* acc, float w, const uint4& r) {
    const uint32_t rr[4] = {r.x, r.y, r.z, r.w};
    #pragma unroll
    for (int c = 0; c < 4; c++) {
        __nv_bfloat162 b = *(const __nv_bfloat162*)&rr[c];
        acc[c * 2 + 0] = fmaf(w, __bfloat162float(b.x), acc[c * 2 + 0]);
        acc[c * 2 + 1] = fmaf(w, __bfloat162float(b.y), acc[c * 2 + 1]);
    }
}

__global__ __launch_bounds__(384) void sampler_kernel(const uint4* __restrict__ val,
                                                      const float* __restrict__ ref,
                                                      const float* __restrict__ oa,
                                                      uint4* __restrict__ out) {
    int q0 = blockIdx.x * 4;
    int tid = threadIdx.x;
    __shared__ float s[4][72];
    __shared__ float pw[96][4];   // softmax*bilinear weights for 4 corners
    __shared__ int   po[96][4];   // clamped corner offsets (uint4 units)
    if (tid < 288) s[tid / 72][tid % 72] = oa[(size_t)(q0 + tid / 72) * NOA + tid % 72];
    __syncthreads();

    if (tid < 96) {
        int lq = tid / 24, hp = tid % 24;
        int h = hp >> 2, p = hp & 3;
        const float* sq = s[lq];
        int q = q0 + lq;

        float lg0 = sq[48 + h * 4 + 0], lg1 = sq[48 + h * 4 + 1];
        float lg2 = sq[48 + h * 4 + 2], lg3 = sq[48 + h * 4 + 3];
        float mx = fmaxf(fmaxf(lg0, lg1), fmaxf(lg2, lg3));
        float se = __expf(lg0 - mx) + __expf(lg1 - mx) + __expf(lg2 - mx) + __expf(lg3 - mx);
        float wp = __expf(sq[48 + h * 4 + p] - mx) / se;

        float px = ref[q * 2]     * (float)GRID + sq[(h * 4 + p) * 2]     - 0.5f;
        float py = ref[q * 2 + 1] * (float)GRID + sq[(h * 4 + p) * 2 + 1] - 0.5f;
        float fx0 = floorf(px), fy0 = floorf(py);
        int x0 = (int)fx0, y0 = (int)fy0;
        float fx = px - fx0, fy = py - fy0;

        float vx0 = ((unsigned)x0 < (unsigned)GRID) ? 1.f : 0.f;
        float vx1 = ((unsigned)(x0 + 1) < (unsigned)GRID) ? 1.f : 0.f;
        float vy0 = ((unsigned)y0 < (unsigned)GRID) ? 1.f : 0.f;
        float vy1 = ((unsigned)(y0 + 1) < (unsigned)GRID) ? 1.f : 0.f;
        pw[tid][0] = wp * (1.f - fy) * (1.f - fx) * vy0 * vx0;
        pw[tid][1] = wp * (1.f - fy) * fx         * vy0 * vx1;
        pw[tid][2] = wp * fy         * (1.f - fx) * vy1 * vx0;
        pw[tid][3] = wp * fy         * fx         * vy1 * vx1;

        int x0c = min(GRID - 1, max(0, x0)), x1c = min(GRID - 1, max(0, x0 + 1));
        int y0c = min(GRID - 1, max(0, y0)), y1c = min(GRID - 1, max(0, y0 + 1));
        po[tid][0] = (y0c * GRID + x0c) * (C / 8);
        po[tid][1] = (y0c * GRID + x1c) * (C / 8);
        po[tid][2] = (y1c * GRID + x0c) * (C / 8);
        po[tid][3] = (y1c * GRID + x1c) * (C / 8);
    }
    __syncthreads();

    int lq = tid / 96;       // which query in the block
    int t = tid % 96;        // channel octet 0..95
    int h = t >> 4;          // head (16 octets = 128 channels)
    int q = q0 + lq;
    int base = lq * 24 + h * 4;

    float acc[8] = {};
    #pragma unroll
    for (int p = 0; p < NP; p++) {
        float4 w = *(const float4*)pw[base + p];
        int4 o4 = *(const int4*)po[base + p];
        uint4 r00 = __ldg(&val[o4.x + t]);
        uint4 r01 = __ldg(&val[o4.y + t]);
        uint4 r10 = __ldg(&val[o4.z + t]);
        uint4 r11 = __ldg(&val[o4.w + t]);
        accum8(acc, w.x, r00);
        accum8(acc, w.y, r01);
        accum8(acc, w.z, r10);
        accum8(acc, w.w, r11);
    }
    uint4 packed;
    __nv_bfloat162 p0 = __floats2bfloat162_rn(acc[0], acc[1]);
    __nv_bfloat162 p1 = __floats2bfloat162_rn(acc[2], acc[3]);
    __nv_bfloat162 p2 = __floats2bfloat162_rn(acc[4], acc[5]);
    __nv_bfloat162 p3 = __floats2bfloat162_rn(acc[6], acc[7]);
    packed.x = *(uint32_t*)&p0;
    packed.y = *(uint32_t*)&p1;
    packed.z = *(uint32_t*)&p2;
    packed.w = *(uint32_t*)&p3;
    out[(size_t)q * (C / 8) + t] = packed;
}

// ---------------- host side ----------------
extern "C" void kernel_launch(void* const* d_in, const int* in_sizes, int n_in,
                              void* d_out, int out_size) {
    const float* query = (const float*)d_in[0];
    const float* ref   = (const float*)d_in[1];
    const float* feat  = (const float*)d_in[2];
    const float* feat2 = (const float*)d_in[3];
    const float* qn_w = (const float*)d_in[6];
    const float* qn_b = (const float*)d_in[7];
    const float* fn_w = (const float*)d_in[8];
    const float* fn_b = (const float*)d_in[9];
    const float* so_w = (const float*)d_in[10];
    const float* so_b = (const float*)d_in[11];
    const float* aw_w = (const float*)d_in[12];
    const float* aw_b = (const float*)d_in[13];
    const float* vp_w = (const float*)d_in[14];
    const float* vp_b = (const float*)d_in[15];
    const float* op_w = (const float*)d_in[16];
    const float* op_b = (const float*)d_in[17];
    const float* gamma = (const float*)d_in[18];
    const float* qn2_w = (const float*)d_in[19];
    const float* qn2_b = (const float*)d_in[20];
    const float* fn2_w = (const float*)d_in[21];
    const float* fn2_b = (const float*)d_in[22];
    const float* so2_w = (const float*)d_in[23];
    const float* so2_b = (const float*)d_in[24];
    const float* aw2_w = (const float*)d_in[25];
    const float* aw2_b = (const float*)d_in[26];
    const float* vp2_w = (const float*)d_in[27];
    const float* vp2_b = (const float*)d_in[28];
    const float* op2_w = (const float*)d_in[29];
    const float* op2_b = (const float*)d_in[30];
    const float* gamma2 = (const float*)d_in[31];
    float* out = (float*)d_out;

    __nv_bfloat16 *p_qn, *p_fn, *p_fn2, *p_samp, *p_val, *p_val2, *pw_vp, *pw_op, *pw_oa;
    float *p_q1, *p_oa, *pb_oa;
    cudaGetSymbolAddress((void**)&p_qn, s_qn);
    cudaGetSymbolAddress((void**)&p_fn, s_fn);
    cudaGetSymbolAddress((void**)&p_fn2, s_fn2);
    cudaGetSymbolAddress((void**)&p_samp, s_samp);
    cudaGetSymbolAddress((void**)&p_val, s_val);
    cudaGetSymbolAddress((void**)&p_val2, s_val2);
    cudaGetSymbolAddress((void**)&pw_vp, w_vp);
    cudaGetSymbolAddress((void**)&pw_op, w_op);
    cudaGetSymbolAddress((void**)&pw_oa, w_oa);
    cudaGetSymbolAddress((void**)&pb_oa, b_oa);
    cudaGetSymbolAddress((void**)&p_q1, g_q1);
    cudaGetSymbolAddress((void**)&p_oa, g_oa);

    static bool attr_done = false;
    if (!attr_done) {
        cudaFuncSetAttribute(gemm_fused3,
                             cudaFuncAttributeMaxDynamicSharedMemorySize, SMEM_GEMM);
        cudaFuncSetAttribute(gemm_bf16<1, false>,
                             cudaFuncAttributeMaxDynamicSharedMemorySize, SMEM_GEMM);
        cudaFuncSetAttribute(gemm_oa,
                             cudaFuncAttributeMaxDynamicSharedMemorySize, SMEM_GEMM);
        attr_done = true;
    }

    const int nW = C * C;
    prep_weights<<<(nW + 255) / 256, 256>>>(vp_w, op_w, vp2_w, op2_w,
                                            so_w, aw_w, so_b, aw_b,
                                            so2_w, aw2_w, so2_b, aw2_b,
                                            pw_vp, pw_op, pw_oa, pb_oa);

    // All stage-independent LNs up front: LN(query), LN(feat), LN(feat2)
    ln_tri<<<3 * LQ, 192>>>(query, qn_w, qn_b, p_qn,
                            feat, fn_w, fn_b, p_fn,
                            feat2, fn2_w, fn2_b, p_fn2);

    // Fused: value-GEMM1, value-GEMM2 (stage-2 hoisted), oa-GEMM1 (2 n-tiles)
    gemm_fused3<<<dim3(14, LQ / MT), 256, SMEM_GEMM>>>(
        p_fn, pw_vp, vp_b, p_val,
        p_fn2, pw_vp + nW, vp2_b, p_val2,
        p_qn, pw_oa, pb_oa, p_oa);

    // Stage 1 tail
    sampler_kernel<<<LQ / 4, 384>>>((const uint4*)p_val, ref, p_oa, (uint4*)p_samp);
    gemm_bf16<1, false><<<dim3(C / GBN, LQ / MT), 256, SMEM_GEMM>>>(
        p_samp, pw_op, op_b, query, gamma, p_q1, C, C);

    // Stage 2 (val2 already computed)
    ln_one<<<LQ, 192>>>(p_q1, qn2_w, qn2_b, p_qn);
    gemm_oa<<<dim3(2, LQ / MT), 256, SMEM_GEMM>>>(
        p_qn, pw_oa + NOA * C, pb_oa + NOA, p_oa);
    sampler_kernel<<<LQ / 4, 384>>>((const uint4*)p_val2, ref, p_oa, (uint4*)p_samp);
    gemm_bf16<1, false><<<dim3(C / GBN, LQ / MT), 256, SMEM_GEMM>>>(
        p_samp, pw_op + nW, op2_b, p_q1, gamma2, out, C, C);
}

// round 15
// speedup vs baseline: 5.5438x; 1.0084x over previous
#include <cuda_runtime.h>
#include <cuda_bf16.h>
#include <cstdint>

#define LQ 9216
#define C 768
#define NH 6
#define DH 128
#define NP 4
#define GRID 96
#define NOA 128   // padded offset+aw output width (48 offs + 24 logits + 56 pad)

// ---------------- scratch (no allocations allowed) ----------------
__device__ __nv_bfloat16 s_qn[LQ * C];
__device__ __nv_bfloat16 s_fn[LQ * C];
__device__ __nv_bfloat16 s_fn2[LQ * C];
__device__ __nv_bfloat16 s_samp[LQ * C];
__device__ __nv_bfloat16 s_val[LQ * C];
__device__ __nv_bfloat16 s_val2[LQ * C];
__device__ __nv_bfloat16 w_vp[2][C * C];
__device__ __nv_bfloat16 w_op[2][C * C];
__device__ __nv_bfloat16 w_oa[2][NOA * C];
__device__ float b_oa[2][NOA];
__device__ float g_q1[LQ * C];
__device__ float g_oa[LQ * NOA];

// ---------------- LayerNorm core ----------------
__device__ __forceinline__ void ln_row(const float* __restrict__ x,
                                       const float* __restrict__ w,
                                       const float* __restrict__ b,
                                       __nv_bfloat16* __restrict__ y, int row) {
    int t = threadIdx.x;
    int lane = t & 31, wid = t >> 5;
    float4 v = ((const float4*)(x + (size_t)row * C))[t];

    __shared__ float part[6];
    float s = v.x + v.y + v.z + v.w;
    #pragma unroll
    for (int o = 16; o; o >>= 1) s += __shfl_down_sync(0xffffffffu, s, o);
    if (!lane) part[wid] = s;
    __syncthreads();
    float mu = (part[0] + part[1] + part[2] + part[3] + part[4] + part[5]) * (1.f / C);

    float dx = v.x - mu, dy = v.y - mu, dz = v.z - mu, dw = v.w - mu;
    s = dx * dx + dy * dy + dz * dz + dw * dw;
    __syncthreads();
    #pragma unroll
    for (int o = 16; o; o >>= 1) s += __shfl_down_sync(0xffffffffu, s, o);
    if (!lane) part[wid] = s;
    __syncthreads();
    float rs = rsqrtf((part[0] + part[1] + part[2] + part[3] + part[4] + part[5]) * (1.f / C) + 1e-6f);

    float4 wv = ((const float4*)w)[t];
    float4 bv = ((const float4*)b)[t];
    __nv_bfloat162 p0 = __floats2bfloat162_rn(dx * rs * wv.x + bv.x, dy * rs * wv.y + bv.y);
    __nv_bfloat162 p1 = __floats2bfloat162_rn(dz * rs * wv.z + bv.z, dw * rs * wv.w + bv.w);
    __nv_bfloat162* yr = (__nv_bfloat162*)(y + (size_t)row * C);
    yr[t * 2] = p0;
    yr[t * 2 + 1] = p1;
}

// ---------------- prelude: 3x LN + all weight prep in ONE launch -------------
// blocks [0, 3*LQ): LN rows. blocks [3*LQ, 3*LQ+3072): weight conversion.
__global__ __launch_bounds__(192) void prelude(
    const float* __restrict__ x0, const float* __restrict__ w0,
    const float* __restrict__ b0, __nv_bfloat16* __restrict__ y0,
    const float* __restrict__ x1, const float* __restrict__ w1,
    const float* __restrict__ b1, __nv_bfloat16* __restrict__ y1,
    const float* __restrict__ x2, const float* __restrict__ w2,
    const float* __restrict__ b2, __nv_bfloat16* __restrict__ y2,
    const float* __restrict__ vp1, const float* __restrict__ op1,
    const float* __restrict__ vp2, const float* __restrict__ op2,
    const float* __restrict__ so1, const float* __restrict__ aw1,
    const float* __restrict__ so1b, const float* __restrict__ aw1b,
    const float* __restrict__ so2, const float* __restrict__ aw2,
    const float* __restrict__ so2b, const float* __restrict__ aw2b,
    __nv_bfloat16* __restrict__ wvp, __nv_bfloat16* __restrict__ wop,
    __nv_bfloat16* __restrict__ woa, float* __restrict__ boa) {
    int row = blockIdx.x;
    if (row < LQ) { ln_row(x0, w0, b0, y0, row); return; }
    if (row < 2 * LQ) { ln_row(x1, w1, b1, y1, row - LQ); return; }
    if (row < 3 * LQ) { ln_row(x2, w2, b2, y2, row - 2 * LQ); return; }

    const int nW = C * C;   // 589824 = 3072 * 192
    int i = (row - 3 * LQ) * 192 + threadIdx.x;
    if (i < nW) {
        wvp[i] = __float2bfloat16(vp1[i]);
        wop[i] = __float2bfloat16(op1[i]);
        wvp[nW + i] = __float2bfloat16(vp2[i]);
        wop[nW + i] = __float2bfloat16(op2[i]);
    }
    if (i < NOA * C) {
        float v1 = 0.f, v2 = 0.f;
        if (i < 48 * C) { v1 = so1[i]; v2 = so2[i]; }
        else if (i < 72 * C) { v1 = aw1[i - 48 * C]; v2 = aw2[i - 48 * C]; }
        woa[i] = __float2bfloat16(v1);
        woa[NOA * C + i] = __float2bfloat16(v2);
    }
    if (i < NOA) {
        boa[i]       = (i < 48) ? so1b[i] : (i < 72 ? aw1b[i - 48] : 0.f);
        boa[NOA + i] = (i < 48) ? so2b[i] : (i < 72 ? aw2b[i - 48] : 0.f);
    }
}

__global__ __launch_bounds__(192) void ln_one(const float* __restrict__ x,
                                              const float* __restrict__ w,
                                              const float* __restrict__ b,
                                              __nv_bfloat16* __restrict__ y) {
    ln_row(x, w, b, y, blockIdx.x);
}

// ---------------- bf16 HMMA GEMM core, 64xNTx32, 3-stage cp.async ------------
#define MT 64
#define GBN 128
#define GBK 32
#define LDA 40   // elements; 80B row stride (16B aligned, reduces conflicts)
#define NSTG 3
#define SMEM_GEMM (NSTG * (MT + GBN) * LDA * 2)   // 46080 B

__device__ __forceinline__ void mma16816(float* c, const uint32_t* a, const uint32_t* b) {
    asm volatile(
        "mma.sync.aligned.m16n8k16.row.col.f32.bf16.bf16.f32 "
        "{%0,%1,%2,%3}, {%4,%5,%6,%7}, {%8,%9}, {%0,%1,%2,%3};\n"
        : "+f"(c[0]), "+f"(c[1]), "+f"(c[2]), "+f"(c[3])
        : "r"(a[0]), "r"(a[1]), "r"(a[2]), "r"(a[3]), "r"(b[0]), "r"(b[1]));
}

__device__ __forceinline__ void cp16(uint32_t s, const void* g) {
    asm volatile("cp.async.cg.shared.global [%0], [%1], 16;\n" :: "r"(s), "l"(g));
}

// MODE 0: out = acc + bias ; MODE 1: out = resid + gamma*(acc+bias)
// NT: n-tile width (128 or 64)
template <int MODE, bool OUT_BF16, int NT>
__device__ __forceinline__ void gemm_core(const __nv_bfloat16* __restrict__ A,
                                          const __nv_bfloat16* __restrict__ B,
                                          const float* __restrict__ bias,
                                          const float* __restrict__ resid,
                                          const float* __restrict__ gamma,
                                          void* __restrict__ Cout,
                                          int N, int K, int bm, int bn,
                                          __nv_bfloat16* smem) {
    const uint32_t STGB = (MT + NT) * LDA * 2;    // bytes per stage
    const uint32_t BOFF = MT * LDA * 2;           // B offset within a stage
    constexpr int NPR = NT / 32;                  // x4-ldmatrix loads for B
    constexpr int NA = NT / 16;                   // n8 MMA tiles per warp

    int tid = threadIdx.x;
    int warp = tid >> 5, lane = tid & 31;
    int wm = (warp >> 1) * 16;                     // 4 warps along m (16 rows each)
    int wn = (warp & 1) * (NT / 2);                // 2 warps along n

    uint32_t sBase = (uint32_t)__cvta_generic_to_shared(smem);

    uint32_t a_addr[2], b_addr[NPR][2];
    #pragma unroll
    for (int ks = 0; ks < 2; ks++)
        a_addr[ks] = sBase +
            ((wm + (lane & 15)) * LDA + ks * 16 + (lane >> 4) * 8) * 2;
    #pragma unroll
    for (int pr = 0; pr < NPR; pr++)
        #pragma unroll
        for (int ks = 0; ks < 2; ks++)
            b_addr[pr][ks] = sBase + BOFF +
                ((wn + pr * 16 + (lane & 15)) * LDA + ks * 16 + (lane >> 4) * 8) * 2;

    const __nv_bfloat16* Abase = A + (size_t)bm * K;
    const __nv_bfloat16* Bbase = B + (size_t)bn * K;

    auto load_stage = [&](int stage, int k0) {
        uint32_t so = sBase + stage * STGB;
        {   // A: 64 rows * 4 chunks = 256 slots, 1 per thread
            int r = tid >> 2, c = (tid & 3) * 8;
            cp16(so + r * (LDA * 2) + c * 2, Abase + (size_t)r * K + k0 + c);
        }
        #pragma unroll
        for (int i = 0; i < NT * 4; i += 256) {   // B: NT rows * 4 chunks
            int idx = i + tid;
            int r = idx >> 2, c = (idx & 3) * 8;
            cp16(so + BOFF + r * (LDA * 2) + c * 2, Bbase + (size_t)r * K + k0 + c);
        }
        asm volatile("cp.async.commit_group;\n");
    };

    float acc[NA][4] = {};

    const int NK = K / GBK;   // 24
    load_stage(0, 0);
    load_stage(1, GBK);

    for (int it = 0; it < NK; it++) {
        if (it + 1 < NK)
            asm volatile("cp.async.wait_group 1;\n");
        else
            asm volatile("cp.async.wait_group 0;\n");
        __syncthreads();

        if (it + 2 < NK) load_stage((it + 2) % NSTG, (it + 2) * GBK);

        uint32_t soff = (it % NSTG) * STGB;
        #pragma unroll
        for (int ks = 0; ks < 2; ks++) {
            uint32_t af[4], bf[NA][2];
            asm volatile("ldmatrix.sync.aligned.m8n8.x4.shared.b16 {%0,%1,%2,%3}, [%4];"
                         : "=r"(af[0]), "=r"(af[1]), "=r"(af[2]), "=r"(af[3])
                         : "r"(a_addr[ks] + soff));
            #pragma unroll
            for (int pr = 0; pr < NPR; pr++) {
                uint32_t r0, r1, r2, r3;
                asm volatile("ldmatrix.sync.aligned.m8n8.x4.shared.b16 {%0,%1,%2,%3}, [%4];"
                             : "=r"(r0), "=r"(r1), "=r"(r2), "=r"(r3)
                             : "r"(b_addr[pr][ks] + soff));
                bf[pr * 2 + 0][0] = r0; bf[pr * 2 + 0][1] = r2;
                bf[pr * 2 + 1][0] = r1; bf[pr * 2 + 1][1] = r3;
            }
            #pragma unroll
            for (int na = 0; na < NA; na++)
                mma16816(acc[na], af, bf[na]);
        }
    }

    int tr = lane >> 2, tc = (lane & 3) * 2;
    #pragma unroll
    for (int half = 0; half < 2; half++) {
        int m = bm + wm + half * 8 + tr;
        #pragma unroll
        for (int na = 0; na < NA; na++) {
            int n = bn + wn + na * 8 + tc;
            float v0 = acc[na][half * 2 + 0] + bias[n];
            float v1 = acc[na][half * 2 + 1] + bias[n + 1];
            if (MODE == 1) {
                v0 = resid[(size_t)m * N + n] + gamma[n] * v0;
                v1 = resid[(size_t)m * N + n + 1] + gamma[n + 1] * v1;
            }
            if (OUT_BF16)
                *(__nv_bfloat162*)((__nv_bfloat16*)Cout + (size_t)m * N + n) =
                    __floats2bfloat162_rn(v0, v1);
            else
                *(float2*)((float*)Cout + (size_t)m * N + n) = make_float2(v0, v1);
        }
    }
}

// Fused: value-GEMM1 (bx 0..5), value-GEMM2 (bx 6..11), oa-GEMM1 (bx 12..13, NT=64)
__global__ __launch_bounds__(256, 3) void gemm_fused3(
    const __nv_bfloat16* __restrict__ A0, const __nv_bfloat16* __restrict__ B0,
    const float* __restrict__ bias0, __nv_bfloat16* __restrict__ out0,
    const __nv_bfloat16* __restrict__ A1, const __nv_bfloat16* __restrict__ B1,
    const float* __restrict__ bias1, __nv_bfloat16* __restrict__ out1,
    const __nv_bfloat16* __restrict__ A2, const __nv_bfloat16* __restrict__ B2,
    const float* __restrict__ bias2, float* __restrict__ out2) {
    extern __shared__ __nv_bfloat16 smem[];
    int bx = blockIdx.x, bm = blockIdx.y * MT;
    if (bx < 6)
        gemm_core<0, true, 128>(A0, B0, bias0, nullptr, nullptr, out0, C, C, bm, bx * GBN, smem);
    else if (bx < 12)
        gemm_core<0, true, 128>(A1, B1, bias1, nullptr, nullptr, out1, C, C, bm, (bx - 6) * GBN, smem);
    else
        gemm_core<0, false, 64>(A2, B2, bias2, nullptr, nullptr, out2, NOA, C, bm, (bx - 12) * 64, smem);
}

// Standalone out-GEMMs (NT=128) and oa-GEMM2 (NT=64)
template <int MODE, bool OUT_BF16>
__global__ __launch_bounds__(256, 3) void gemm_bf16(const __nv_bfloat16* __restrict__ A,
                                                    const __nv_bfloat16* __restrict__ B,
                                                    const float* __restrict__ bias,
                                                    const float* __restrict__ resid,
                                                    const float* __restrict__ gamma,
                                                    void* __restrict__ Cout,
                                                    int N, int K) {
    extern __shared__ __nv_bfloat16 smem[];
    gemm_core<MODE, OUT_BF16, 128>(A, B, bias, resid, gamma, Cout, N, K,
                                   blockIdx.y * MT, blockIdx.x * GBN, smem);
}

__global__ __launch_bounds__(256, 3) void gemm_oa(const __nv_bfloat16* __restrict__ A,
                                                  const __nv_bfloat16* __restrict__ B,
                                                  const float* __restrict__ bias,
                                                  float* __restrict__ Cout) {
    extern __shared__ __nv_bfloat16 smem[];
    gemm_core<0, false, 64>(A, B, bias, nullptr, nullptr, Cout, NOA, C,
                            blockIdx.y * MT, blockIdx.x * 64, smem);
}

// ---------------- bilinear sampling: uint4 gathers, 2-point load batching ----
// Block = 4 queries, 384 threads. Phase 1: 96 threads compute softmax-folded
// bilinear weights (validity folded: weight=0 OOB, clamped index) + offsets.
// Phase 2: per thread, batch-load 8 corner vectors (2 points) before any FMA.
__device__ __forceinline__ void accum8(float* acc, float w, const uint4& r) {
    const uint32_t rr[4] = {r.x, r.y, r.z, r.w};
    #pragma unroll
    for (int c = 0; c < 4; c++) {
        __nv_bfloat162 b = *(const __nv_bfloat162*)&rr[c];
        acc[c * 2 + 0] = fmaf(w, __bfloat162float(b.x), acc[c * 2 + 0]);
        acc[c * 2 + 1] = fmaf(w, __bfloat162float(b.y), acc[c * 2 + 1]);
    }
}

__global__ __launch_bounds__(384) void sampler_kernel(const uint4* __restrict__ val,
                                                      const float* __restrict__ ref,
                                                      const float* __restrict__ oa,
                                                      uint4* __restrict__ out) {
    int q0 = blockIdx.x * 4;
    int tid = threadIdx.x;
    __shared__ float s[4][72];
    __shared__ float pw[96][4];   // softmax*bilinear weights for 4 corners
    __shared__ int   po[96][4];   // clamped corner offsets (uint4 units)
    if (tid < 288) s[tid / 72][tid % 72] = oa[(size_t)(q0 + tid / 72) * NOA + tid % 72];
    __syncthreads();

    if (tid < 96) {
        int lq = tid / 24, hp = tid % 24;
        int h = hp >> 2, p = hp & 3;
        const float* sq = s[lq];
        int q = q0 + lq;

        float lg0 = sq[48 + h * 4 + 0], lg1 = sq[48 + h * 4 + 1];
        float lg2 = sq[48 + h * 4 + 2], lg3 = sq[48 + h * 4 + 3];
        float mx = fmaxf(fmaxf(lg0, lg1), fmaxf(lg2, lg3));
        float se = __expf(lg0 - mx) + __expf(lg1 - mx) + __expf(lg2 - mx) + __expf(lg3 - mx);
        float wp = __expf(sq[48 + h * 4 + p] - mx) / se;

        float px = ref[q * 2]     * (float)GRID + sq[(h * 4 + p) * 2]     - 0.5f;
        float py = ref[q * 2 + 1] * (float)GRID + sq[(h * 4 + p) * 2 + 1] - 0.5f;
        float fx0 = floorf(px), fy0 = floorf(py);
        int x0 = (int)fx0, y0 = (int)fy0;
        float fx = px - fx0, fy = py - fy0;

        float vx0 = ((unsigned)x0 < (unsigned)GRID) ? 1.f : 0.f;
        float vx1 = ((unsigned)(x0 + 1) < (unsigned)GRID) ? 1.f : 0.f;
        float vy0 = ((unsigned)y0 < (unsigned)GRID) ? 1.f : 0.f;
        float vy1 = ((unsigned)(y0 + 1) < (unsigned)GRID) ? 1.f : 0.f;
        pw[tid][0] = wp * (1.f - fy) * (1.f - fx) * vy0 * vx0;
        pw[tid][1] = wp * (1.f - fy) * fx         * vy0 * vx1;
        pw[tid][2] = wp * fy         * (1.f - fx) * vy1 * vx0;
        pw[tid][3] = wp * fy         * fx         * vy1 * vx1;

        int x0c = min(GRID - 1, max(0, x0)), x1c = min(GRID - 1, max(0, x0 + 1));
        int y0c = min(GRID - 1, max(0, y0)), y1c = min(GRID - 1, max(0, y0 + 1));
        po[tid][0] = (y0c * GRID + x0c) * (C / 8);
        po[tid][1] = (y0c * GRID + x1c) * (C / 8);
        po[tid][2] = (y1c * GRID + x0c) * (C / 8);
        po[tid][3] = (y1c * GRID + x1c) * (C / 8);
    }
    __syncthreads();

    int lq = tid / 96;       // which query in the block
    int t = tid % 96;        // channel octet 0..95
    int h = t >> 4;          // head (16 octets = 128 channels)
    int q = q0 + lq;
    int base = lq * 24 + h * 4;

    float acc[8] = {};
    #pragma unroll
    for (int pp = 0; pp < 2; pp++) {
        float4 wA = *(const float4*)pw[base + 2 * pp + 0];
        float4 wB = *(const float4*)pw[base + 2 * pp + 1];
        int4 oA = *(const int4*)po[base + 2 * pp + 0];
        int4 oB = *(const int4*)po[base + 2 * pp + 1];
        // issue all 8 loads before consuming any (MLP=8)
        uint4 rA0 = __ldg(&val[oA.x + t]);
        uint4 rA1 = __ldg(&val[oA.y + t]);
        uint4 rA2 = __ldg(&val[oA.z + t]);
        uint4 rA3 = __ldg(&val[oA.w + t]);
        uint4 rB0 = __ldg(&val[oB.x + t]);
        uint4 rB1 = __ldg(&val[oB.y + t]);
        uint4 rB2 = __ldg(&val[oB.z + t]);
        uint4 rB3 = __ldg(&val[oB.w + t]);
        accum8(acc, wA.x, rA0);
        accum8(acc, wA.y, rA1);
        accum8(acc, wA.z, rA2);
        accum8(acc, wA.w, rA3);
        accum8(acc, wB.x, rB0);
        accum8(acc, wB.y, rB1);
        accum8(acc, wB.z, rB2);
        accum8(acc, wB.w, rB3);
    }
    uint4 packed;
    __nv_bfloat162 p0 = __floats2bfloat162_rn(acc[0], acc[1]);
    __nv_bfloat162 p1 = __floats2bfloat162_rn(acc[2], acc[3]);
    __nv_bfloat162 p2 = __floats2bfloat162_rn(acc[4], acc[5]);
    __nv_bfloat162 p3 = __floats2bfloat162_rn(acc[6], acc[7]);
    packed.x = *(uint32_t*)&p0;
    packed.y = *(uint32_t*)&p1;
    packed.z = *(uint32_t*)&p2;
    packed.w = *(uint32_t*)&p3;
    out[(size_t)q * (C / 8) + t] = packed;
}

// ---------------- host side ----------------
extern "C" void kernel_launch(void* const* d_in, const int* in_sizes, int n_in,
                              void* d_out, int out_size) {
    const float* query = (const float*)d_in[0];
    const float* ref   = (const float*)d_in[1];
    const float* feat  = (const float*)d_in[2];
    const float* feat2 = (const float*)d_in[3];
    const float* qn_w = (const float*)d_in[6];
    const float* qn_b = (const float*)d_in[7];
    const float* fn_w = (const float*)d_in[8];
    const float* fn_b = (const float*)d_in[9];
    const float* so_w = (const float*)d_in[10];
    const float* so_b = (const float*)d_in[11];
    const float* aw_w = (const float*)d_in[12];
    const float* aw_b = (const float*)d_in[13];
    const float* vp_w = (const float*)d_in[14];
    const float* vp_b = (const float*)d_in[15];
    const float* op_w = (const float*)d_in[16];
    const float* op_b = (const float*)d_in[17];
    const float* gamma = (const float*)d_in[18];
    const float* qn2_w = (const float*)d_in[19];
    const float* qn2_b = (const float*)d_in[20];
    const float* fn2_w = (const float*)d_in[21];
    const float* fn2_b = (const float*)d_in[22];
    const float* so2_w = (const float*)d_in[23];
    const float* so2_b = (const float*)d_in[24];
    const float* aw2_w = (const float*)d_in[25];
    const float* aw2_b = (const float*)d_in[26];
    const float* vp2_w = (const float*)d_in[27];
    const float* vp2_b = (const float*)d_in[28];
    const float* op2_w = (const float*)d_in[29];
    const float* op2_b = (const float*)d_in[30];
    const float* gamma2 = (const float*)d_in[31];
    float* out = (float*)d_out;

    __nv_bfloat16 *p_qn, *p_fn, *p_fn2, *p_samp, *p_val, *p_val2, *pw_vp, *pw_op, *pw_oa;
    float *p_q1, *p_oa, *pb_oa;
    cudaGetSymbolAddress((void**)&p_qn, s_qn);
    cudaGetSymbolAddress((void**)&p_fn, s_fn);
    cudaGetSymbolAddress((void**)&p_fn2, s_fn2);
    cudaGetSymbolAddress((void**)&p_samp, s_samp);
    cudaGetSymbolAddress((void**)&p_val, s_val);
    cudaGetSymbolAddress((void**)&p_val2, s_val2);
    cudaGetSymbolAddress((void**)&pw_vp, w_vp);
    cudaGetSymbolAddress((void**)&pw_op, w_op);
    cudaGetSymbolAddress((void**)&pw_oa, w_oa);
    cudaGetSymbolAddress((void**)&pb_oa, b_oa);
    cudaGetSymbolAddress((void**)&p_q1, g_q1);
    cudaGetSymbolAddress((void**)&p_oa, g_oa);

    static bool attr_done = false;
    if (!attr_done) {
        cudaFuncSetAttribute(gemm_fused3,
                             cudaFuncAttributeMaxDynamicSharedMemorySize, SMEM_GEMM);
        cudaFuncSetAttribute(gemm_bf16<1, false>,
                             cudaFuncAttributeMaxDynamicSharedMemorySize, SMEM_GEMM);
        cudaFuncSetAttribute(gemm_oa,
                             cudaFuncAttributeMaxDynamicSharedMemorySize, SMEM_GEMM);
        attr_done = true;
    }

    // Prelude: LN(query), LN(feat), LN(feat2) + all weight conversion, 1 launch
    prelude<<<3 * LQ + 3072, 192>>>(query, qn_w, qn_b, p_qn,
                                    feat, fn_w, fn_b, p_fn,
                                    feat2, fn2_w, fn2_b, p_fn2,
                                    vp_w, op_w, vp2_w, op2_w,
                                    so_w, aw_w, so_b, aw_b,
                                    so2_w, aw2_w, so2_b, aw2_b,
                                    pw_vp, pw_op, pw_oa, pb_oa);

    const int nW = C * C;
    // Fused: value-GEMM1, value-GEMM2 (stage-2 hoisted), oa-GEMM1 (2 n-tiles)
    gemm_fused3<<<dim3(14, LQ / MT), 256, SMEM_GEMM>>>(
        p_fn, pw_vp, vp_b, p_val,
        p_fn2, pw_vp + nW, vp2_b, p_val2,
        p_qn, pw_oa, pb_oa, p_oa);

    // Stage 1 tail
    sampler_kernel<<<LQ / 4, 384>>>((const uint4*)p_val, ref, p_oa, (uint4*)p_samp);
    gemm_bf16<1, false><<<dim3(C / GBN, LQ / MT), 256, SMEM_GEMM>>>(
        p_samp, pw_op, op_b, query, gamma, p_q1, C, C);

    // Stage 2 (val2 already computed)
    ln_one<<<LQ, 192>>>(p_q1, qn2_w, qn2_b, p_qn);
    gemm_oa<<<dim3(2, LQ / MT), 256, SMEM_GEMM>>>(
        p_qn, pw_oa + NOA * C, pb_oa + NOA, p_oa);
    sampler_kernel<<<LQ / 4, 384>>>((const uint4*)p_val2, ref, p_oa, (uint4*)p_samp);
    gemm_bf16<1, false><<<dim3(C / GBN, LQ / MT), 256, SMEM_GEMM>>>(
        p_samp, pw_op + nW, op2_b, p_q1, gamma2, out, C, C);
}